// round 2
// baseline (speedup 1.0000x reference)
#include <cuda_runtime.h>
#include <math.h>

#define BATCH 4
#define DIMC  256
#define DI    256
#define NS    16
#define NPT   4096
#define NC    64
#define CL    64

// ---------------- scratch (device globals; no allocation) ----------------
static __device__ float g_xp[BATCH*512*NPT];        // in_proj output [b][o][n]
static __device__ float g_xsT[BATCH*NPT*DI];        // silu(conv(x1)) [b][n][d]
static __device__ float g_deltaT[BATCH*NPT*DI];     // sigmoid(z)     [b][n][d]
static __device__ float g_Bm[BATCH*NPT*NS];         // [b][n][s]
static __device__ float g_Cm[BATCH*NPT*NS];
static __device__ float g_y[BATCH*NPT*DI];          // ssm output     [b][n][d]
static __device__ float g_P[BATCH*NC*NS*DI];        // chunk partials [b][c][s][d]
static __device__ float g_H0[BATCH*NC*NS*DI];       // chunk init     [b][c][s][d]
static __device__ float g_A[DI*NS];
static __device__ float g_aL[DI*NS];
static __device__ float g_xTres[BATCH*NPT*DIMC];    // residual x^T   [b][n][c]
static __device__ float g_opre[BATCH*NPT*DIMC];     // pre-LN out     [b][n][c]

// ---------------- K0: transpose x -> xTres --------------------------------
__global__ void k_transpose(const float* __restrict__ x) {
    __shared__ float s[32][33];
    int b = blockIdx.z;
    int c0 = blockIdx.y * 32, n0 = blockIdx.x * 32;
    int tx = threadIdx.x, ty = threadIdx.y;   // 32 x 8
    #pragma unroll
    for (int i = 0; i < 32; i += 8)
        s[ty + i][tx] = x[((size_t)b*DIMC + (c0+ty+i))*NPT + n0 + tx];
    __syncthreads();
    #pragma unroll
    for (int i = 0; i < 32; i += 8)
        g_xTres[((size_t)b*NPT + (n0+ty+i))*DIMC + c0 + tx] = s[tx][ty + i];
}

// ---------------- Kpre: A = -exp(A_log), aL = A^CL -------------------------
__global__ void k_pre(const float* __restrict__ A_log) {
    int i = blockIdx.x * 256 + threadIdx.x;
    if (i < DI*NS) {
        float al = A_log[i];
        g_A[i]  = -expf(al);
        g_aL[i] =  expf((float)CL * al);   // CL even -> (-e^al)^CL = e^(CL*al)
    }
}

// ---------------- K1: in_proj SGEMM: xp[b][o][n] ---------------------------
// W[512][256] * x[b][256][4096], BM=128 BN=128 BK=16, 256 thr, 8x8 tiles
__global__ void k_inproj(const float* __restrict__ W, const float* __restrict__ X,
                         const float* __restrict__ bias) {
    __shared__ float As[16][132];
    __shared__ float Bs[16][128];
    int b = blockIdx.z, ot = blockIdx.y, nt = blockIdx.x;
    int tid = threadIdx.x;
    const float* Xb = X + (size_t)b*DIMC*NPT;
    float acc[8][8];
    #pragma unroll
    for (int i = 0; i < 8; i++)
        #pragma unroll
        for (int j = 0; j < 8; j++) acc[i][j] = 0.f;
    int tr = tid >> 4, tc = tid & 15;

    for (int k0 = 0; k0 < DIMC; k0 += 16) {
        {   // A tile (transposed scatter): 128 o x 16 k
            int ar = tid >> 1;
            int kb = (tid & 1) * 8;
            const float* src = &W[(size_t)(ot*128 + ar)*DIMC + k0 + kb];
            float4 v0 = *(const float4*)src;
            float4 v1 = *(const float4*)(src + 4);
            As[kb+0][ar] = v0.x; As[kb+1][ar] = v0.y; As[kb+2][ar] = v0.z; As[kb+3][ar] = v0.w;
            As[kb+4][ar] = v1.x; As[kb+5][ar] = v1.y; As[kb+6][ar] = v1.z; As[kb+7][ar] = v1.w;
        }
        {   // B tile: 16 k x 128 n
            #pragma unroll
            for (int i = 0; i < 2; i++) {
                int f = tid*2 + i;                 // 0..511 float4s
                int r = f >> 5, c4 = f & 31;
                *(float4*)&Bs[r][c4*4] =
                    *(const float4*)&Xb[(size_t)(k0+r)*NPT + nt*128 + c4*4];
            }
        }
        __syncthreads();
        #pragma unroll
        for (int k = 0; k < 16; k++) {
            float ra[8], rb[8];
            #pragma unroll
            for (int i = 0; i < 8; i++) ra[i] = As[k][tr*8 + i];
            #pragma unroll
            for (int j = 0; j < 8; j++) rb[j] = Bs[k][tc*8 + j];
            #pragma unroll
            for (int i = 0; i < 8; i++)
                #pragma unroll
                for (int j = 0; j < 8; j++)
                    acc[i][j] = fmaf(ra[i], rb[j], acc[i][j]);
        }
        __syncthreads();
    }
    #pragma unroll
    for (int i = 0; i < 8; i++) {
        int o = ot*128 + tr*8 + i;
        float bi = bias[o];
        float* dst = &g_xp[((size_t)b*512 + o)*NPT + nt*128 + tc*8];
        #pragma unroll
        for (int j = 0; j < 8; j++) dst[j] = acc[i][j] + bi;
    }
}

// ---------------- K2: conv+silu+sigmoid+transpose + B/C proj ---------------
// Block: (ntile of 64, b). smem: bufA[256][69], sxs[256][65], sBw/sCw[16][256]
#define K2_SMEM ((256*69 + 256*65 + 2*16*256) * 4)
__global__ void k_conv_bc(const float* __restrict__ Bw, const float* __restrict__ Cw,
                          const float* __restrict__ wconv, const float* __restrict__ bconv) {
    extern __shared__ float sm[];
    float* bufA = sm;                        // [256][69]
    float* sxs  = sm + 256*69;               // [256][65]
    float* sBw  = sxs + 256*65;              // [16][256]
    float* sCw  = sBw + 16*256;
    int b = blockIdx.y, nt = blockIdx.x;
    int n0 = nt * 64;
    int tid = threadIdx.x;
    int tx = tid & 31, ty = tid >> 5;        // 32 x 8
    const float* xpb = g_xp + (size_t)b*512*NPT;

    for (int i = tid; i < 16*256; i += 256) { sBw[i] = Bw[i]; sCw[i] = Cw[i]; }
    // x1 tile with left halo of 3 (causal pad with zeros)
    for (int d = ty; d < 256; d += 8)
        for (int c = tx; c < 67; c += 32) {
            int n = n0 - 3 + c;
            bufA[d*69 + c] = (n >= 0) ? xpb[(size_t)d*NPT + n] : 0.f;
        }
    __syncthreads();

    {   // depthwise conv + silu, one d-row per thread
        int d = tid;
        float w0 = wconv[d*4+0], w1 = wconv[d*4+1], w2 = wconv[d*4+2], w3 = wconv[d*4+3];
        float bc = bconv[d];
        const float* r = &bufA[d*69];
        #pragma unroll 4
        for (int n = 0; n < 64; n++) {
            float v = fmaf(w3, r[n+3], fmaf(w2, r[n+2], fmaf(w1, r[n+1], fmaf(w0, r[n], bc))));
            sxs[d*65 + n] = v / (1.f + expf(-v));
        }
    }
    __syncthreads();

    {   // transposed write of xs
        float* dst = g_xsT + (size_t)b*NPT*DI;
        #pragma unroll 4
        for (int n = 0; n < 64; n++)
            dst[(size_t)(n0+n)*DI + tid] = sxs[tid*65 + n];
    }
    {   // B/C projections: thread = (n, group); group: 0=Bm[0:8] 1=Bm[8:16] 2=Cm[0:8] 3=Cm[8:16]
        int n = tid & 63;
        int g = tid >> 6;
        const float* wp = ((g < 2) ? sBw : sCw) + (g & 1) * 8 * 256;
        float acc[8];
        #pragma unroll
        for (int s = 0; s < 8; s++) acc[s] = 0.f;
        for (int d = 0; d < 256; d++) {
            float xv = sxs[d*65 + n];
            #pragma unroll
            for (int s = 0; s < 8; s++)
                acc[s] = fmaf(xv, wp[s*256 + d], acc[s]);
        }
        float* outp = ((g < 2) ? g_Bm : g_Cm) + ((size_t)b*NPT + n0 + n)*NS + (g & 1)*8;
        #pragma unroll
        for (int s = 0; s < 8; s++) outp[s] = acc[s];
    }
    __syncthreads();
    // z tile: sigmoid at load, reuse bufA
    for (int d = ty; d < 256; d += 8)
        for (int c = tx; c < 64; c += 32) {
            float zv = xpb[(size_t)(256 + d)*NPT + n0 + c];
            bufA[d*69 + c] = 1.f / (1.f + expf(-zv));
        }
    __syncthreads();
    {   // transposed write of delta
        float* dst = g_deltaT + (size_t)b*NPT*DI;
        #pragma unroll 4
        for (int n = 0; n < 64; n++)
            dst[(size_t)(n0+n)*DI + tid] = bufA[tid*69 + n];
    }
}

// ---------------- K3 (S1): per-chunk local scan -> P ----------------------
__global__ void k_scan1() {
    __shared__ float sB[CL*NS];
    int b = blockIdx.y, ch = blockIdx.x;
    int tid = threadIdx.x;                   // = d
    int t0 = ch * CL;
    for (int i = tid; i < CL*NS; i += 256)
        sB[i] = g_Bm[((size_t)b*NPT + t0)*NS + i];
    __syncthreads();
    float A[NS], h[NS];
    #pragma unroll
    for (int s = 0; s < NS; s++) { A[s] = g_A[tid*NS + s]; h[s] = 0.f; }
    const float* dptr = g_deltaT + ((size_t)b*NPT + t0)*DI + tid;
    for (int k = 0; k < CL; k++) {
        float dl = dptr[(size_t)k*DI];
        const float* Bk = &sB[k*NS];
        #pragma unroll
        for (int s = 0; s < NS; s++)
            h[s] = fmaf(A[s], h[s], dl * Bk[s]);
    }
    float* P = g_P + ((size_t)b*NC + ch)*NS*DI + tid;
    #pragma unroll
    for (int s = 0; s < NS; s++) P[s*DI] = h[s];
}

// ---------------- K4 (S2): inter-chunk prefix ------------------------------
__global__ void k_scan2() {
    int g = blockIdx.x * 256 + threadIdx.x;  // 0..16383
    int d = g & 255;
    int s = (g >> 8) & 15;
    int b = g >> 12;
    float aL = g_aL[d*NS + s];
    float h = 0.f;
    size_t base = ((size_t)b*NC*NS + s)*DI + d;
    for (int c = 0; c < NC; c++) {
        size_t idx = base + (size_t)c*NS*DI;
        g_H0[idx] = h;
        h = fmaf(aL, h, g_P[idx]);
    }
}

// ---------------- K5 (S3): final scan + output y ---------------------------
__global__ void k_scan3(const float* __restrict__ Dskip) {
    __shared__ float sB[CL*NS], sC[CL*NS];
    int b = blockIdx.y, ch = blockIdx.x;
    int tid = threadIdx.x;                   // = d
    int t0 = ch * CL;
    for (int i = tid; i < CL*NS; i += 256) {
        sB[i] = g_Bm[((size_t)b*NPT + t0)*NS + i];
        sC[i] = g_Cm[((size_t)b*NPT + t0)*NS + i];
    }
    __syncthreads();
    float A[NS], h[NS];
    size_t hbase = ((size_t)b*NC + ch)*NS*DI + tid;
    #pragma unroll
    for (int s = 0; s < NS; s++) { A[s] = g_A[tid*NS + s]; h[s] = g_H0[hbase + s*DI]; }
    float dsk = Dskip[tid];
    const float* dptr = g_deltaT + ((size_t)b*NPT + t0)*DI + tid;
    const float* xptr = g_xsT   + ((size_t)b*NPT + t0)*DI + tid;
    float* yptr       = g_y     + ((size_t)b*NPT + t0)*DI + tid;
    for (int k = 0; k < CL; k++) {
        float dl = dptr[(size_t)k*DI];
        float xv = xptr[(size_t)k*DI];
        const float* Bk = &sB[k*NS];
        const float* Ck = &sC[k*NS];
        float y = dsk * xv;
        #pragma unroll
        for (int s = 0; s < NS; s++) {
            h[s] = fmaf(A[s], h[s], dl * Bk[s]);
            y = fmaf(h[s], Ck[s], y);
        }
        yptr[(size_t)k*DI] = y;
    }
}

// ---------------- K6a: out_proj SGEMM + bias + residual --------------------
// opre[row][c] = sum_d y[row][d]*Wo[c][d] + b_out[c] + xTres[row][c]
__global__ void k_outproj(const float* __restrict__ Wo, const float* __restrict__ bout) {
    __shared__ float As[16][132];   // [k][row]
    __shared__ float Bs[16][132];   // [k][c]
    int mt = blockIdx.x, ntc = blockIdx.y;
    int tid = threadIdx.x;
    float acc[8][8];
    #pragma unroll
    for (int i = 0; i < 8; i++)
        #pragma unroll
        for (int j = 0; j < 8; j++) acc[i][j] = 0.f;
    int tr = tid >> 4, tc = tid & 15;

    for (int k0 = 0; k0 < 256; k0 += 16) {
        {
            int r = tid >> 1, kb = (tid & 1) * 8;
            const float* src = &g_y[(size_t)(mt*128 + r)*DI + k0 + kb];
            float4 v0 = *(const float4*)src;
            float4 v1 = *(const float4*)(src + 4);
            As[kb+0][r] = v0.x; As[kb+1][r] = v0.y; As[kb+2][r] = v0.z; As[kb+3][r] = v0.w;
            As[kb+4][r] = v1.x; As[kb+5][r] = v1.y; As[kb+6][r] = v1.z; As[kb+7][r] = v1.w;
        }
        {
            int c = tid >> 1, kb = (tid & 1) * 8;
            const float* src = &Wo[(size_t)(ntc*128 + c)*DI + k0 + kb];
            float4 v0 = *(const float4*)src;
            float4 v1 = *(const float4*)(src + 4);
            Bs[kb+0][c] = v0.x; Bs[kb+1][c] = v0.y; Bs[kb+2][c] = v0.z; Bs[kb+3][c] = v0.w;
            Bs[kb+4][c] = v1.x; Bs[kb+5][c] = v1.y; Bs[kb+6][c] = v1.z; Bs[kb+7][c] = v1.w;
        }
        __syncthreads();
        #pragma unroll
        for (int k = 0; k < 16; k++) {
            float ra[8], rb[8];
            #pragma unroll
            for (int i = 0; i < 8; i++) ra[i] = As[k][tr*8 + i];
            #pragma unroll
            for (int j = 0; j < 8; j++) rb[j] = Bs[k][tc*8 + j];
            #pragma unroll
            for (int i = 0; i < 8; i++)
                #pragma unroll
                for (int j = 0; j < 8; j++)
                    acc[i][j] = fmaf(ra[i], rb[j], acc[i][j]);
        }
        __syncthreads();
    }
    #pragma unroll
    for (int i = 0; i < 8; i++) {
        size_t row = (size_t)(mt*128 + tr*8 + i);
        const float* res = &g_xTres[row*DIMC + ntc*128 + tc*8];
        float* dst       = &g_opre [row*DIMC + ntc*128 + tc*8];
        #pragma unroll
        for (int j = 0; j < 8; j++) {
            int c = ntc*128 + tc*8 + j;
            dst[j] = acc[i][j] + bout[c] + res[j];
        }
    }
}

// ---------------- K6b: LayerNorm over C + transposed store -----------------
__global__ void k_ln(const float* __restrict__ gamma, const float* __restrict__ beta,
                     float* __restrict__ out) {
    __shared__ float s[256][33];   // [c][n]
    __shared__ float mu[32], rs[32];
    int b = blockIdx.y, nt = blockIdx.x;   // nt: 128 tiles of 32 rows
    int n0 = nt * 32;
    int tid = threadIdx.x;
    for (int i = tid; i < 32*256; i += 256) {
        int n = i >> 8, c = i & 255;
        s[c][n] = g_opre[((size_t)b*NPT + n0 + n)*DIMC + c];
    }
    __syncthreads();
    if (tid < 32) {
        float sum = 0.f, sq = 0.f;
        for (int c = 0; c < 256; c++) { float v = s[c][tid]; sum += v; sq += v*v; }
        float m = sum * (1.f/256.f);
        float var = sq * (1.f/256.f) - m*m;
        mu[tid] = m; rs[tid] = rsqrtf(var + 1e-5f);
    }
    __syncthreads();
    for (int i = tid; i < 32*256; i += 256) {
        int n = i & 31, c = i >> 5;
        float v = (s[c][n] - mu[n]) * rs[n] * gamma[c] + beta[c];
        out[((size_t)b*DIMC + c)*NPT + n0 + n] = v;
    }
}

// ---------------- launch ----------------------------------------------------
extern "C" void kernel_launch(void* const* d_in, const int* in_sizes, int n_in,
                              void* d_out, int out_size) {
    const float* x      = (const float*)d_in[0];
    const float* w_in   = (const float*)d_in[1];
    const float* b_in   = (const float*)d_in[2];
    const float* w_conv = (const float*)d_in[3];
    const float* b_conv = (const float*)d_in[4];
    const float* A_log  = (const float*)d_in[5];
    const float* D_skip = (const float*)d_in[6];
    const float* Bw     = (const float*)d_in[7];
    const float* Cw     = (const float*)d_in[8];
    const float* w_out  = (const float*)d_in[9];
    const float* b_out  = (const float*)d_in[10];
    const float* gamma  = (const float*)d_in[11];
    const float* beta   = (const float*)d_in[12];
    float* out = (float*)d_out;

    cudaFuncSetAttribute(k_conv_bc, cudaFuncAttributeMaxDynamicSharedMemorySize, K2_SMEM);

    k_pre<<<16, 256>>>(A_log);
    k_transpose<<<dim3(128, 8, BATCH), dim3(32, 8)>>>(x);
    k_inproj<<<dim3(32, 4, BATCH), 256>>>(w_in, x, b_in);
    k_conv_bc<<<dim3(64, BATCH), 256, K2_SMEM>>>(Bw, Cw, w_conv, b_conv);
    k_scan1<<<dim3(NC, BATCH), 256>>>();
    k_scan2<<<64, 256>>>();
    k_scan3<<<dim3(NC, BATCH), 256>>>(D_skip);
    k_outproj<<<dim3(128, 2), 256>>>(w_out, b_out);
    k_ln<<<dim3(128, BATCH), 256>>>(gamma, beta, out);
}

// round 3
// speedup vs baseline: 1.2298x; 1.2298x over previous
#include <cuda_runtime.h>
#include <math.h>

#define BATCH 4
#define DIMC  256
#define DI    256
#define NS    16
#define NPT   4096
#define NC    64
#define CL    64

// ---------------- scratch (device globals; no allocation) ----------------
static __device__ float g_xp[BATCH*512*NPT];        // in_proj output [b][o][n]
static __device__ float g_xsT[BATCH*NPT*DI];        // silu(conv(x1)) [b][n][d]
static __device__ float g_deltaT[BATCH*NPT*DI];     // sigmoid(z)     [b][n][d]
static __device__ float g_Bm[BATCH*NPT*NS];         // [b][n][s]
static __device__ float g_Cm[BATCH*NPT*NS];
static __device__ float g_y[BATCH*NPT*DI];          // ssm output     [b][n][d]
static __device__ float g_P[BATCH*NC*NS*DI];        // chunk partials [b][c][s][d]
static __device__ float g_H0[BATCH*NC*NS*DI];       // chunk init     [b][c][s][d]
static __device__ float g_A[DI*NS];
static __device__ float g_aL[DI*NS];
static __device__ float g_xTres[BATCH*NPT*DIMC];    // residual x^T   [b][n][c]
static __device__ float g_opre[BATCH*NPT*DIMC];     // pre-LN out     [b][n][c]

// ---------------- K0: transpose x -> xTres --------------------------------
__global__ void k_transpose(const float* __restrict__ x) {
    __shared__ float s[32][33];
    int b = blockIdx.z;
    int c0 = blockIdx.y * 32, n0 = blockIdx.x * 32;
    int tx = threadIdx.x, ty = threadIdx.y;   // 32 x 8
    #pragma unroll
    for (int i = 0; i < 32; i += 8)
        s[ty + i][tx] = x[((size_t)b*DIMC + (c0+ty+i))*NPT + n0 + tx];
    __syncthreads();
    #pragma unroll
    for (int i = 0; i < 32; i += 8)
        g_xTres[((size_t)b*NPT + (n0+ty+i))*DIMC + c0 + tx] = s[tx][ty + i];
}

// ---------------- Kpre: A = -exp(A_log), aL = A^CL -------------------------
__global__ void k_pre(const float* __restrict__ A_log) {
    int i = blockIdx.x * 256 + threadIdx.x;
    if (i < DI*NS) {
        float al = A_log[i];
        g_A[i]  = -expf(al);
        g_aL[i] =  expf((float)CL * al);   // CL even -> (-e^al)^CL = e^(CL*al)
    }
}

// ---------------- K1: in_proj SGEMM: xp[b][o][n] ---------------------------
__global__ void k_inproj(const float* __restrict__ W, const float* __restrict__ X,
                         const float* __restrict__ bias) {
    __shared__ float As[16][132];
    __shared__ float Bs[16][128];
    int b = blockIdx.z, ot = blockIdx.y, nt = blockIdx.x;
    int tid = threadIdx.x;
    const float* Xb = X + (size_t)b*DIMC*NPT;
    float acc[8][8];
    #pragma unroll
    for (int i = 0; i < 8; i++)
        #pragma unroll
        for (int j = 0; j < 8; j++) acc[i][j] = 0.f;
    int tr = tid >> 4, tc = tid & 15;

    for (int k0 = 0; k0 < DIMC; k0 += 16) {
        {
            int ar = tid >> 1;
            int kb = (tid & 1) * 8;
            const float* src = &W[(size_t)(ot*128 + ar)*DIMC + k0 + kb];
            float4 v0 = *(const float4*)src;
            float4 v1 = *(const float4*)(src + 4);
            As[kb+0][ar] = v0.x; As[kb+1][ar] = v0.y; As[kb+2][ar] = v0.z; As[kb+3][ar] = v0.w;
            As[kb+4][ar] = v1.x; As[kb+5][ar] = v1.y; As[kb+6][ar] = v1.z; As[kb+7][ar] = v1.w;
        }
        {
            #pragma unroll
            for (int i = 0; i < 2; i++) {
                int f = tid*2 + i;
                int r = f >> 5, c4 = f & 31;
                *(float4*)&Bs[r][c4*4] =
                    *(const float4*)&Xb[(size_t)(k0+r)*NPT + nt*128 + c4*4];
            }
        }
        __syncthreads();
        #pragma unroll
        for (int k = 0; k < 16; k++) {
            float ra[8], rb[8];
            #pragma unroll
            for (int i = 0; i < 8; i++) ra[i] = As[k][tr*8 + i];
            #pragma unroll
            for (int j = 0; j < 8; j++) rb[j] = Bs[k][tc*8 + j];
            #pragma unroll
            for (int i = 0; i < 8; i++)
                #pragma unroll
                for (int j = 0; j < 8; j++)
                    acc[i][j] = fmaf(ra[i], rb[j], acc[i][j]);
        }
        __syncthreads();
    }
    #pragma unroll
    for (int i = 0; i < 8; i++) {
        int o = ot*128 + tr*8 + i;
        float bi = bias[o];
        float* dst = &g_xp[((size_t)b*512 + o)*NPT + nt*128 + tc*8];
        #pragma unroll
        for (int j = 0; j < 8; j++) dst[j] = acc[i][j] + bi;
    }
}

// ---------------- K2a: conv+silu+transpose x1, sigmoid+transpose z ---------
// Block handles (b, 32 d-rows, 128 n-cols). 32x8 threads.
#define CZ_P1 133   // 133 mod 32 = 5 (coprime) -> conflict-free column reads
#define CZ_P2 129   // 129 mod 32 = 1 -> conflict-free
__global__ void k_convz(const float* __restrict__ wconv, const float* __restrict__ bconv) {
    __shared__ float s1[32*CZ_P1];
    __shared__ float s2[32*CZ_P2];
    int b = blockIdx.z, dt = blockIdx.y, nt = blockIdx.x;
    int d0 = dt*32, n0 = nt*128;
    int tid = threadIdx.x;
    int tx = tid & 31, ty = tid >> 5;   // 32 x 8
    const float* xpb = g_xp + (size_t)b*512*NPT;

    for (int r = ty; r < 32; r += 8) {
        const float* src = &xpb[(size_t)(d0+r)*NPT + n0 - 3];
        for (int c = tx; c < 131; c += 32) {
            int n = n0 - 3 + c;
            s1[r*CZ_P1 + c] = (n >= 0) ? src[c] : 0.f;
        }
        const float* zsrc = &xpb[(size_t)(256 + d0 + r)*NPT + n0];
        for (int c = tx; c < 128; c += 32)
            s2[r*CZ_P2 + c] = 1.f / (1.f + expf(-zsrc[c]));
    }
    __syncthreads();

    int d = d0 + tx;
    float w0 = wconv[d*4+0], w1 = wconv[d*4+1], w2 = wconv[d*4+2], w3 = wconv[d*4+3];
    float bc = bconv[d];
    float* xdst = g_xsT   + ((size_t)b*NPT + n0)*DI + d;
    float* ddst = g_deltaT + ((size_t)b*NPT + n0)*DI + d;
    const float* r1 = &s1[tx*CZ_P1];
    const float* r2 = &s2[tx*CZ_P2];
    #pragma unroll 4
    for (int n = ty; n < 128; n += 8) {
        float v = fmaf(w3, r1[n+3], fmaf(w2, r1[n+2], fmaf(w1, r1[n+1], fmaf(w0, r1[n], bc))));
        xdst[(size_t)n*DI] = v / (1.f + expf(-v));
        ddst[(size_t)n*DI] = r2[n];
    }
}

// ---------------- K2b: fused B/C SGEMM: [16384 rows x 32 cols x 256 k] -----
// cols 0..15 -> Bm, 16..31 -> Cm. BM=128, BN=32, BK=32, 256 thr, 4x4 tiles.
__global__ void k_bcgemm(const float* __restrict__ Bw, const float* __restrict__ Cw) {
    __shared__ float As[32][132];   // [k][row]
    __shared__ float Bs[32][32];    // [k][col]
    int rt = blockIdx.x;            // 128 blocks
    int tid = threadIdx.x;
    int tr = tid >> 3, tc = tid & 7;   // 32 row-groups x 8 col-groups
    float acc[4][4];
    #pragma unroll
    for (int i = 0; i < 4; i++)
        #pragma unroll
        for (int j = 0; j < 4; j++) acc[i][j] = 0.f;

    for (int k0 = 0; k0 < 256; k0 += 32) {
        #pragma unroll
        for (int i = 0; i < 4; i++) {
            int f = tid + i*256;           // 0..1023 float4s
            int row = f >> 3, c4 = f & 7;
            float4 v = *(const float4*)&g_xsT[(size_t)(rt*128 + row)*DI + k0 + c4*4];
            As[c4*4+0][row] = v.x; As[c4*4+1][row] = v.y;
            As[c4*4+2][row] = v.z; As[c4*4+3][row] = v.w;
        }
        {
            int col = tid >> 3, c4 = tid & 7;
            const float* wr = (col < 16) ? &Bw[(size_t)col*256] : &Cw[(size_t)(col-16)*256];
            float4 v = *(const float4*)&wr[k0 + c4*4];
            Bs[c4*4+0][col] = v.x; Bs[c4*4+1][col] = v.y;
            Bs[c4*4+2][col] = v.z; Bs[c4*4+3][col] = v.w;
        }
        __syncthreads();
        #pragma unroll
        for (int k = 0; k < 32; k++) {
            float ra[4], rb[4];
            #pragma unroll
            for (int i = 0; i < 4; i++) ra[i] = As[k][tr*4 + i];
            #pragma unroll
            for (int j = 0; j < 4; j++) rb[j] = Bs[k][tc*4 + j];
            #pragma unroll
            for (int i = 0; i < 4; i++)
                #pragma unroll
                for (int j = 0; j < 4; j++)
                    acc[i][j] = fmaf(ra[i], rb[j], acc[i][j]);
        }
        __syncthreads();
    }
    float* base = (tc < 4) ? g_Bm : g_Cm;
    int cb = (tc & 3) * 4;
    #pragma unroll
    for (int i = 0; i < 4; i++) {
        size_t row = (size_t)(rt*128 + tr*4 + i);
        #pragma unroll
        for (int j = 0; j < 4; j++)
            base[row*NS + cb + j] = acc[i][j];
    }
}

// ---------------- K3 (S1): per-chunk local scan -> P ----------------------
__global__ void k_scan1() {
    __shared__ float sB[CL*NS];
    int b = blockIdx.y, ch = blockIdx.x;
    int tid = threadIdx.x;                   // = d
    int t0 = ch * CL;
    for (int i = tid; i < CL*NS; i += 256)
        sB[i] = g_Bm[((size_t)b*NPT + t0)*NS + i];
    __syncthreads();
    float A[NS], h[NS];
    #pragma unroll
    for (int s = 0; s < NS; s++) { A[s] = g_A[tid*NS + s]; h[s] = 0.f; }
    const float* dptr = g_deltaT + ((size_t)b*NPT + t0)*DI + tid;
    for (int k = 0; k < CL; k++) {
        float dl = dptr[(size_t)k*DI];
        const float* Bk = &sB[k*NS];
        #pragma unroll
        for (int s = 0; s < NS; s++)
            h[s] = fmaf(A[s], h[s], dl * Bk[s]);
    }
    float* P = g_P + ((size_t)b*NC + ch)*NS*DI + tid;
    #pragma unroll
    for (int s = 0; s < NS; s++) P[s*DI] = h[s];
}

// ---------------- K4 (S2): inter-chunk prefix ------------------------------
__global__ void k_scan2() {
    int g = blockIdx.x * 256 + threadIdx.x;  // 0..16383
    int d = g & 255;
    int s = (g >> 8) & 15;
    int b = g >> 12;
    float aL = g_aL[d*NS + s];
    float h = 0.f;
    size_t base = ((size_t)b*NC*NS + s)*DI + d;
    for (int c = 0; c < NC; c++) {
        size_t idx = base + (size_t)c*NS*DI;
        g_H0[idx] = h;
        h = fmaf(aL, h, g_P[idx]);
    }
}

// ---------------- K5 (S3): final scan + output y ---------------------------
__global__ void k_scan3(const float* __restrict__ Dskip) {
    __shared__ float sB[CL*NS], sC[CL*NS];
    int b = blockIdx.y, ch = blockIdx.x;
    int tid = threadIdx.x;                   // = d
    int t0 = ch * CL;
    for (int i = tid; i < CL*NS; i += 256) {
        sB[i] = g_Bm[((size_t)b*NPT + t0)*NS + i];
        sC[i] = g_Cm[((size_t)b*NPT + t0)*NS + i];
    }
    __syncthreads();
    float A[NS], h[NS];
    size_t hbase = ((size_t)b*NC + ch)*NS*DI + tid;
    #pragma unroll
    for (int s = 0; s < NS; s++) { A[s] = g_A[tid*NS + s]; h[s] = g_H0[hbase + s*DI]; }
    float dsk = Dskip[tid];
    const float* dptr = g_deltaT + ((size_t)b*NPT + t0)*DI + tid;
    const float* xptr = g_xsT   + ((size_t)b*NPT + t0)*DI + tid;
    float* yptr       = g_y     + ((size_t)b*NPT + t0)*DI + tid;
    for (int k = 0; k < CL; k++) {
        float dl = dptr[(size_t)k*DI];
        float xv = xptr[(size_t)k*DI];
        const float* Bk = &sB[k*NS];
        const float* Ck = &sC[k*NS];
        float y = dsk * xv;
        #pragma unroll
        for (int s = 0; s < NS; s++) {
            h[s] = fmaf(A[s], h[s], dl * Bk[s]);
            y = fmaf(h[s], Ck[s], y);
        }
        yptr[(size_t)k*DI] = y;
    }
}

// ---------------- K6a: out_proj SGEMM + bias + residual --------------------
__global__ void k_outproj(const float* __restrict__ Wo, const float* __restrict__ bout) {
    __shared__ float As[16][132];   // [k][row]
    __shared__ float Bs[16][132];   // [k][c]
    int mt = blockIdx.x, ntc = blockIdx.y;
    int tid = threadIdx.x;
    float acc[8][8];
    #pragma unroll
    for (int i = 0; i < 8; i++)
        #pragma unroll
        for (int j = 0; j < 8; j++) acc[i][j] = 0.f;
    int tr = tid >> 4, tc = tid & 15;

    for (int k0 = 0; k0 < 256; k0 += 16) {
        {
            int r = tid >> 1, kb = (tid & 1) * 8;
            const float* src = &g_y[(size_t)(mt*128 + r)*DI + k0 + kb];
            float4 v0 = *(const float4*)src;
            float4 v1 = *(const float4*)(src + 4);
            As[kb+0][r] = v0.x; As[kb+1][r] = v0.y; As[kb+2][r] = v0.z; As[kb+3][r] = v0.w;
            As[kb+4][r] = v1.x; As[kb+5][r] = v1.y; As[kb+6][r] = v1.z; As[kb+7][r] = v1.w;
        }
        {
            int c = tid >> 1, kb = (tid & 1) * 8;
            const float* src = &Wo[(size_t)(ntc*128 + c)*DI + k0 + kb];
            float4 v0 = *(const float4*)src;
            float4 v1 = *(const float4*)(src + 4);
            Bs[kb+0][c] = v0.x; Bs[kb+1][c] = v0.y; Bs[kb+2][c] = v0.z; Bs[kb+3][c] = v0.w;
            Bs[kb+4][c] = v1.x; Bs[kb+5][c] = v1.y; Bs[kb+6][c] = v1.z; Bs[kb+7][c] = v1.w;
        }
        __syncthreads();
        #pragma unroll
        for (int k = 0; k < 16; k++) {
            float ra[8], rb[8];
            #pragma unroll
            for (int i = 0; i < 8; i++) ra[i] = As[k][tr*8 + i];
            #pragma unroll
            for (int j = 0; j < 8; j++) rb[j] = Bs[k][tc*8 + j];
            #pragma unroll
            for (int i = 0; i < 8; i++)
                #pragma unroll
                for (int j = 0; j < 8; j++)
                    acc[i][j] = fmaf(ra[i], rb[j], acc[i][j]);
        }
        __syncthreads();
    }
    #pragma unroll
    for (int i = 0; i < 8; i++) {
        size_t row = (size_t)(mt*128 + tr*8 + i);
        const float* res = &g_xTres[row*DIMC + ntc*128 + tc*8];
        float* dst       = &g_opre [row*DIMC + ntc*128 + tc*8];
        #pragma unroll
        for (int j = 0; j < 8; j++) {
            int c = ntc*128 + tc*8 + j;
            dst[j] = acc[i][j] + bout[c] + res[j];
        }
    }
}

// ---------------- K6b: LayerNorm over C + transposed store -----------------
__global__ void k_ln(const float* __restrict__ gamma, const float* __restrict__ beta,
                     float* __restrict__ out) {
    __shared__ float s[256][33];   // [c][n]
    __shared__ float mu[32], rs[32];
    int b = blockIdx.y, nt = blockIdx.x;
    int n0 = nt * 32;
    int tid = threadIdx.x;
    for (int i = tid; i < 32*256; i += 256) {
        int n = i >> 8, c = i & 255;
        s[c][n] = g_opre[((size_t)b*NPT + n0 + n)*DIMC + c];
    }
    __syncthreads();
    if (tid < 32) {
        float sum = 0.f, sq = 0.f;
        for (int c = 0; c < 256; c++) { float v = s[c][tid]; sum += v; sq += v*v; }
        float m = sum * (1.f/256.f);
        float var = sq * (1.f/256.f) - m*m;
        mu[tid] = m; rs[tid] = rsqrtf(var + 1e-5f);
    }
    __syncthreads();
    for (int i = tid; i < 32*256; i += 256) {
        int n = i & 31, c = i >> 5;
        float v = (s[c][n] - mu[n]) * rs[n] * gamma[c] + beta[c];
        out[((size_t)b*DIMC + c)*NPT + n0 + n] = v;
    }
}

// ---------------- launch ----------------------------------------------------
extern "C" void kernel_launch(void* const* d_in, const int* in_sizes, int n_in,
                              void* d_out, int out_size) {
    const float* x      = (const float*)d_in[0];
    const float* w_in   = (const float*)d_in[1];
    const float* b_in   = (const float*)d_in[2];
    const float* w_conv = (const float*)d_in[3];
    const float* b_conv = (const float*)d_in[4];
    const float* A_log  = (const float*)d_in[5];
    const float* D_skip = (const float*)d_in[6];
    const float* Bw     = (const float*)d_in[7];
    const float* Cw     = (const float*)d_in[8];
    const float* w_out  = (const float*)d_in[9];
    const float* b_out  = (const float*)d_in[10];
    const float* gamma  = (const float*)d_in[11];
    const float* beta   = (const float*)d_in[12];
    float* out = (float*)d_out;

    k_pre<<<16, 256>>>(A_log);
    k_transpose<<<dim3(128, 8, BATCH), dim3(32, 8)>>>(x);
    k_inproj<<<dim3(32, 4, BATCH), 256>>>(w_in, x, b_in);
    k_convz<<<dim3(32, 8, BATCH), 256>>>(w_conv, b_conv);
    k_bcgemm<<<128, 256>>>(Bw, Cw);
    k_scan1<<<dim3(NC, BATCH), 256>>>();
    k_scan2<<<64, 256>>>();
    k_scan3<<<dim3(NC, BATCH), 256>>>(D_skip);
    k_outproj<<<dim3(128, 2), 256>>>(w_out, b_out);
    k_ln<<<dim3(128, BATCH), 256>>>(gamma, beta, out);
}

// round 4
// speedup vs baseline: 1.2728x; 1.0350x over previous
#include <cuda_runtime.h>
#include <math.h>

#define BATCH 4
#define DIMC  256
#define DI    256
#define NS    16
#define NPT   4096
#define NC    64
#define CL    64

typedef unsigned long long u64;

// ---- f32x2 packed-FMA helpers (sm_103a; ptxas never emits these itself) ----
__device__ __forceinline__ void ffma2(u64 &d, u64 a, u64 b) {
    asm("fma.rn.f32x2 %0, %1, %2, %0;" : "+l"(d) : "l"(a), "l"(b));
}
__device__ __forceinline__ u64 dup2(float x) {
    u64 r; asm("mov.b64 %0, {%1, %1};" : "=l"(r) : "f"(x)); return r;
}
__device__ __forceinline__ u64 pack2(float lo, float hi) {
    u64 r; asm("mov.b64 %0, {%1, %2};" : "=l"(r) : "f"(lo), "f"(hi)); return r;
}
__device__ __forceinline__ void unpack2(u64 v, float &lo, float &hi) {
    asm("mov.b64 {%0, %1}, %2;" : "=f"(lo), "=f"(hi) : "l"(v));
}

// ---------------- scratch (device globals; no allocation) ----------------
static __device__ float g_xp[BATCH*512*NPT];        // in_proj output [b][o][n]
static __device__ float g_xsT[BATCH*NPT*DI];        // silu(conv(x1)) [b][n][d]
static __device__ float g_deltaT[BATCH*NPT*DI];     // sigmoid(z)     [b][n][d]
static __device__ float g_Bm[BATCH*NPT*NS];         // [b][n][s]
static __device__ float g_Cm[BATCH*NPT*NS];
static __device__ float g_y[BATCH*NPT*DI];          // ssm output     [b][n][d]
static __device__ float g_P[BATCH*NC*NS*DI];        // chunk partials [b][c][s][d]
static __device__ float g_H0[BATCH*NC*NS*DI];       // chunk init     [b][c][s][d]
static __device__ float g_A[DI*NS];
static __device__ float g_aL[DI*NS];
static __device__ float g_opre[BATCH*NPT*DIMC];     // pre-LN out (no residual) [b][n][c]

// ---------------- Kpre: A = -exp(A_log), aL = A^CL -------------------------
__global__ void k_pre(const float* __restrict__ A_log) {
    int i = blockIdx.x * 256 + threadIdx.x;
    if (i < DI*NS) {
        float al = A_log[i];
        g_A[i]  = -expf(al);
        g_aL[i] =  expf((float)CL * al);   // CL even -> (-e^al)^CL = e^(CL*al)
    }
}

// ---------------- K1: in_proj SGEMM (f32x2): xp[b][o][n] -------------------
__global__ void k_inproj(const float* __restrict__ W, const float* __restrict__ X,
                         const float* __restrict__ bias) {
    __shared__ float As[16][132];
    __shared__ float Bs[16][128];
    int b = blockIdx.z, ot = blockIdx.y, nt = blockIdx.x;
    int tid = threadIdx.x;
    const float* Xb = X + (size_t)b*DIMC*NPT;
    u64 acc2[8][4];
    #pragma unroll
    for (int i = 0; i < 8; i++)
        #pragma unroll
        for (int j = 0; j < 4; j++) acc2[i][j] = 0ull;
    int tr = tid >> 4, tc = tid & 15;

    for (int k0 = 0; k0 < DIMC; k0 += 16) {
        {
            int ar = tid >> 1;
            int kb = (tid & 1) * 8;
            const float* src = &W[(size_t)(ot*128 + ar)*DIMC + k0 + kb];
            float4 v0 = *(const float4*)src;
            float4 v1 = *(const float4*)(src + 4);
            As[kb+0][ar] = v0.x; As[kb+1][ar] = v0.y; As[kb+2][ar] = v0.z; As[kb+3][ar] = v0.w;
            As[kb+4][ar] = v1.x; As[kb+5][ar] = v1.y; As[kb+6][ar] = v1.z; As[kb+7][ar] = v1.w;
        }
        {
            #pragma unroll
            for (int i = 0; i < 2; i++) {
                int f = tid*2 + i;
                int r = f >> 5, c4 = f & 31;
                *(float4*)&Bs[r][c4*4] =
                    *(const float4*)&Xb[(size_t)(k0+r)*NPT + nt*128 + c4*4];
            }
        }
        __syncthreads();
        #pragma unroll
        for (int k = 0; k < 16; k++) {
            u64 a2[8], b2[4];
            #pragma unroll
            for (int i = 0; i < 8; i++) a2[i] = dup2(As[k][tr*8 + i]);
            #pragma unroll
            for (int j = 0; j < 4; j++) {
                float2 v = *(const float2*)&Bs[k][tc*8 + j*2];
                b2[j] = pack2(v.x, v.y);
            }
            #pragma unroll
            for (int i = 0; i < 8; i++)
                #pragma unroll
                for (int j = 0; j < 4; j++)
                    ffma2(acc2[i][j], a2[i], b2[j]);
        }
        __syncthreads();
    }
    #pragma unroll
    for (int i = 0; i < 8; i++) {
        int o = ot*128 + tr*8 + i;
        float bi = bias[o];
        float* dst = &g_xp[((size_t)b*512 + o)*NPT + nt*128 + tc*8];
        #pragma unroll
        for (int j = 0; j < 4; j++) {
            float lo, hi; unpack2(acc2[i][j], lo, hi);
            dst[j*2]   = lo + bi;
            dst[j*2+1] = hi + bi;
        }
    }
}

// ---------------- K2a: conv+silu+transpose x1, sigmoid+transpose z ---------
#define CZ_P1 133
#define CZ_P2 129
__global__ void k_convz(const float* __restrict__ wconv, const float* __restrict__ bconv) {
    __shared__ float s1[32*CZ_P1];
    __shared__ float s2[32*CZ_P2];
    int b = blockIdx.z, dt = blockIdx.y, nt = blockIdx.x;
    int d0 = dt*32, n0 = nt*128;
    int tid = threadIdx.x;
    int tx = tid & 31, ty = tid >> 5;   // 32 x 8
    const float* xpb = g_xp + (size_t)b*512*NPT;

    for (int r = ty; r < 32; r += 8) {
        const float* src = &xpb[(size_t)(d0+r)*NPT + n0 - 3];
        for (int c = tx; c < 131; c += 32) {
            int n = n0 - 3 + c;
            s1[r*CZ_P1 + c] = (n >= 0) ? src[c] : 0.f;
        }
        const float* zsrc = &xpb[(size_t)(256 + d0 + r)*NPT + n0];
        for (int c = tx; c < 128; c += 32)
            s2[r*CZ_P2 + c] = __fdividef(1.f, 1.f + __expf(-zsrc[c]));
    }
    __syncthreads();

    int d = d0 + tx;
    float w0 = wconv[d*4+0], w1 = wconv[d*4+1], w2 = wconv[d*4+2], w3 = wconv[d*4+3];
    float bc = bconv[d];
    float* xdst = g_xsT    + ((size_t)b*NPT + n0)*DI + d;
    float* ddst = g_deltaT + ((size_t)b*NPT + n0)*DI + d;
    const float* r1 = &s1[tx*CZ_P1];
    const float* r2 = &s2[tx*CZ_P2];
    #pragma unroll 4
    for (int n = ty; n < 128; n += 8) {
        float v = fmaf(w3, r1[n+3], fmaf(w2, r1[n+2], fmaf(w1, r1[n+1], fmaf(w0, r1[n], bc))));
        xdst[(size_t)n*DI] = __fdividef(v, 1.f + __expf(-v));
        ddst[(size_t)n*DI] = r2[n];
    }
}

// ---------------- K2b: fused B/C SGEMM (f32x2) ------------------------------
__global__ void k_bcgemm(const float* __restrict__ Bw, const float* __restrict__ Cw) {
    __shared__ float As[32][132];   // [k][row]
    __shared__ float Bs[32][32];    // [k][col]
    int rt = blockIdx.x;            // 128 blocks
    int tid = threadIdx.x;
    int tr = tid >> 3, tc = tid & 7;   // 32 row-groups x 8 col-groups
    u64 acc2[4][2];
    #pragma unroll
    for (int i = 0; i < 4; i++) { acc2[i][0] = 0ull; acc2[i][1] = 0ull; }

    for (int k0 = 0; k0 < 256; k0 += 32) {
        #pragma unroll
        for (int i = 0; i < 4; i++) {
            int f = tid + i*256;
            int row = f >> 3, c4 = f & 7;
            float4 v = *(const float4*)&g_xsT[(size_t)(rt*128 + row)*DI + k0 + c4*4];
            As[c4*4+0][row] = v.x; As[c4*4+1][row] = v.y;
            As[c4*4+2][row] = v.z; As[c4*4+3][row] = v.w;
        }
        {
            int col = tid >> 3, c4 = tid & 7;
            const float* wr = (col < 16) ? &Bw[(size_t)col*256] : &Cw[(size_t)(col-16)*256];
            float4 v = *(const float4*)&wr[k0 + c4*4];
            Bs[c4*4+0][col] = v.x; Bs[c4*4+1][col] = v.y;
            Bs[c4*4+2][col] = v.z; Bs[c4*4+3][col] = v.w;
        }
        __syncthreads();
        #pragma unroll
        for (int k = 0; k < 32; k++) {
            u64 a2[4], b2[2];
            #pragma unroll
            for (int i = 0; i < 4; i++) a2[i] = dup2(As[k][tr*4 + i]);
            #pragma unroll
            for (int j = 0; j < 2; j++) {
                float2 v = *(const float2*)&Bs[k][tc*4 + j*2];
                b2[j] = pack2(v.x, v.y);
            }
            #pragma unroll
            for (int i = 0; i < 4; i++) {
                ffma2(acc2[i][0], a2[i], b2[0]);
                ffma2(acc2[i][1], a2[i], b2[1]);
            }
        }
        __syncthreads();
    }
    float* base = (tc < 4) ? g_Bm : g_Cm;
    int cb = (tc & 3) * 4;
    #pragma unroll
    for (int i = 0; i < 4; i++) {
        size_t row = (size_t)(rt*128 + tr*4 + i);
        float v0, v1, v2, v3;
        unpack2(acc2[i][0], v0, v1);
        unpack2(acc2[i][1], v2, v3);
        base[row*NS + cb + 0] = v0; base[row*NS + cb + 1] = v1;
        base[row*NS + cb + 2] = v2; base[row*NS + cb + 3] = v3;
    }
}

// ---------------- K3 (S1): per-chunk local scan -> P ----------------------
__global__ void k_scan1() {
    __shared__ float sB[CL*NS];
    int b = blockIdx.y, ch = blockIdx.x;
    int tid = threadIdx.x;                   // = d
    int t0 = ch * CL;
    for (int i = tid; i < CL*NS; i += 256)
        sB[i] = g_Bm[((size_t)b*NPT + t0)*NS + i];
    __syncthreads();
    float A[NS], h[NS];
    #pragma unroll
    for (int s = 0; s < NS; s++) { A[s] = g_A[tid*NS + s]; h[s] = 0.f; }
    const float* dptr = g_deltaT + ((size_t)b*NPT + t0)*DI + tid;
    for (int k = 0; k < CL; k++) {
        float dl = dptr[(size_t)k*DI];
        const float* Bk = &sB[k*NS];
        #pragma unroll
        for (int s = 0; s < NS; s++)
            h[s] = fmaf(A[s], h[s], dl * Bk[s]);
    }
    float* P = g_P + ((size_t)b*NC + ch)*NS*DI + tid;
    #pragma unroll
    for (int s = 0; s < NS; s++) P[s*DI] = h[s];
}

// ---------------- K4 (S2): inter-chunk prefix ------------------------------
__global__ void k_scan2() {
    int g = blockIdx.x * 256 + threadIdx.x;  // 0..16383
    int d = g & 255;
    int s = (g >> 8) & 15;
    int b = g >> 12;
    float aL = g_aL[d*NS + s];
    float h = 0.f;
    size_t base = ((size_t)b*NC*NS + s)*DI + d;
    for (int c = 0; c < NC; c++) {
        size_t idx = base + (size_t)c*NS*DI;
        g_H0[idx] = h;
        h = fmaf(aL, h, g_P[idx]);
    }
}

// ---------------- K5 (S3): final scan + output y ---------------------------
__global__ void k_scan3(const float* __restrict__ Dskip) {
    __shared__ float sB[CL*NS], sC[CL*NS];
    int b = blockIdx.y, ch = blockIdx.x;
    int tid = threadIdx.x;                   // = d
    int t0 = ch * CL;
    for (int i = tid; i < CL*NS; i += 256) {
        sB[i] = g_Bm[((size_t)b*NPT + t0)*NS + i];
        sC[i] = g_Cm[((size_t)b*NPT + t0)*NS + i];
    }
    __syncthreads();
    float A[NS], h[NS];
    size_t hbase = ((size_t)b*NC + ch)*NS*DI + tid;
    #pragma unroll
    for (int s = 0; s < NS; s++) { A[s] = g_A[tid*NS + s]; h[s] = g_H0[hbase + s*DI]; }
    float dsk = Dskip[tid];
    const float* dptr = g_deltaT + ((size_t)b*NPT + t0)*DI + tid;
    const float* xptr = g_xsT   + ((size_t)b*NPT + t0)*DI + tid;
    float* yptr       = g_y     + ((size_t)b*NPT + t0)*DI + tid;
    for (int k = 0; k < CL; k++) {
        float dl = dptr[(size_t)k*DI];
        float xv = xptr[(size_t)k*DI];
        const float* Bk = &sB[k*NS];
        const float* Ck = &sC[k*NS];
        float y = dsk * xv;
        #pragma unroll
        for (int s = 0; s < NS; s++) {
            h[s] = fmaf(A[s], h[s], dl * Bk[s]);
            y = fmaf(h[s], Ck[s], y);
        }
        yptr[(size_t)k*DI] = y;
    }
}

// ---------------- K6a: out_proj SGEMM (f32x2) + bias ------------------------
__global__ void k_outproj(const float* __restrict__ Wo, const float* __restrict__ bout) {
    __shared__ float As[16][132];   // [k][row]
    __shared__ float Bs[16][132];   // [k][c]
    int mt = blockIdx.x, ntc = blockIdx.y;
    int tid = threadIdx.x;
    u64 acc2[8][4];
    #pragma unroll
    for (int i = 0; i < 8; i++)
        #pragma unroll
        for (int j = 0; j < 4; j++) acc2[i][j] = 0ull;
    int tr = tid >> 4, tc = tid & 15;

    for (int k0 = 0; k0 < 256; k0 += 16) {
        {
            int r = tid >> 1, kb = (tid & 1) * 8;
            const float* src = &g_y[(size_t)(mt*128 + r)*DI + k0 + kb];
            float4 v0 = *(const float4*)src;
            float4 v1 = *(const float4*)(src + 4);
            As[kb+0][r] = v0.x; As[kb+1][r] = v0.y; As[kb+2][r] = v0.z; As[kb+3][r] = v0.w;
            As[kb+4][r] = v1.x; As[kb+5][r] = v1.y; As[kb+6][r] = v1.z; As[kb+7][r] = v1.w;
        }
        {
            int c = tid >> 1, kb = (tid & 1) * 8;
            const float* src = &Wo[(size_t)(ntc*128 + c)*DI + k0 + kb];
            float4 v0 = *(const float4*)src;
            float4 v1 = *(const float4*)(src + 4);
            Bs[kb+0][c] = v0.x; Bs[kb+1][c] = v0.y; Bs[kb+2][c] = v0.z; Bs[kb+3][c] = v0.w;
            Bs[kb+4][c] = v1.x; Bs[kb+5][c] = v1.y; Bs[kb+6][c] = v1.z; Bs[kb+7][c] = v1.w;
        }
        __syncthreads();
        #pragma unroll
        for (int k = 0; k < 16; k++) {
            u64 a2[8], b2[4];
            #pragma unroll
            for (int i = 0; i < 8; i++) a2[i] = dup2(As[k][tr*8 + i]);
            #pragma unroll
            for (int j = 0; j < 4; j++) {
                float2 v = *(const float2*)&Bs[k][tc*8 + j*2];
                b2[j] = pack2(v.x, v.y);
            }
            #pragma unroll
            for (int i = 0; i < 8; i++)
                #pragma unroll
                for (int j = 0; j < 4; j++)
                    ffma2(acc2[i][j], a2[i], b2[j]);
        }
        __syncthreads();
    }
    #pragma unroll
    for (int i = 0; i < 8; i++) {
        size_t row = (size_t)(mt*128 + tr*8 + i);
        float* dst = &g_opre[row*DIMC + ntc*128 + tc*8];
        #pragma unroll
        for (int j = 0; j < 4; j++) {
            int c = ntc*128 + tc*8 + j*2;
            float lo, hi; unpack2(acc2[i][j], lo, hi);
            dst[j*2]   = lo + bout[c];
            dst[j*2+1] = hi + bout[c+1];
        }
    }
}

// ---------------- K6b: residual + LayerNorm over C + transposed store ------
__global__ void k_ln(const float* __restrict__ x,
                     const float* __restrict__ gamma, const float* __restrict__ beta,
                     float* __restrict__ out) {
    __shared__ float s[256][33];   // [c][n]
    __shared__ float mu[32], rs[32];
    int b = blockIdx.y, nt = blockIdx.x;
    int n0 = nt * 32;
    int tid = threadIdx.x;
    // pass 1: opre, coalesced over c
    for (int i = tid; i < 32*256; i += 256) {
        int n = i >> 8, c = i & 255;
        s[c][n] = g_opre[((size_t)b*NPT + n0 + n)*DIMC + c];
    }
    __syncthreads();
    // pass 2: residual from x, coalesced over n
    for (int i = tid; i < 32*256; i += 256) {
        int c = i >> 5, n = i & 31;
        s[c][n] += x[((size_t)b*DIMC + c)*NPT + n0 + n];
    }
    __syncthreads();
    if (tid < 32) {
        float sum = 0.f, sq = 0.f;
        for (int c = 0; c < 256; c++) { float v = s[c][tid]; sum += v; sq += v*v; }
        float m = sum * (1.f/256.f);
        float var = sq * (1.f/256.f) - m*m;
        mu[tid] = m; rs[tid] = rsqrtf(var + 1e-5f);
    }
    __syncthreads();
    for (int i = tid; i < 32*256; i += 256) {
        int n = i & 31, c = i >> 5;
        float v = (s[c][n] - mu[n]) * rs[n] * gamma[c] + beta[c];
        out[((size_t)b*DIMC + c)*NPT + n0 + n] = v;
    }
}

// ---------------- launch ----------------------------------------------------
extern "C" void kernel_launch(void* const* d_in, const int* in_sizes, int n_in,
                              void* d_out, int out_size) {
    const float* x      = (const float*)d_in[0];
    const float* w_in   = (const float*)d_in[1];
    const float* b_in   = (const float*)d_in[2];
    const float* w_conv = (const float*)d_in[3];
    const float* b_conv = (const float*)d_in[4];
    const float* A_log  = (const float*)d_in[5];
    const float* D_skip = (const float*)d_in[6];
    const float* Bw     = (const float*)d_in[7];
    const float* Cw     = (const float*)d_in[8];
    const float* w_out  = (const float*)d_in[9];
    const float* b_out  = (const float*)d_in[10];
    const float* gamma  = (const float*)d_in[11];
    const float* beta   = (const float*)d_in[12];
    float* out = (float*)d_out;

    k_pre<<<16, 256>>>(A_log);
    k_inproj<<<dim3(32, 4, BATCH), 256>>>(w_in, x, b_in);
    k_convz<<<dim3(32, 8, BATCH), 256>>>(w_conv, b_conv);
    k_bcgemm<<<128, 256>>>(Bw, Cw);
    k_scan1<<<dim3(NC, BATCH), 256>>>();
    k_scan2<<<64, 256>>>();
    k_scan3<<<dim3(NC, BATCH), 256>>>(D_skip);
    k_outproj<<<dim3(128, 2), 256>>>(w_out, b_out);
    k_ln<<<dim3(128, BATCH), 256>>>(x, gamma, beta, out);
}

// round 6
// speedup vs baseline: 1.9932x; 1.5660x over previous
#include <cuda_runtime.h>
#include <cuda_bf16.h>
#include <math.h>
#include <stdint.h>

#define BATCH 4
#define DIMC  256
#define DI    256
#define NS    16
#define NPT   4096
#define NC    64
#define CL    64

typedef unsigned long long u64;

// ---- f32x2 packed-FMA helpers ----
__device__ __forceinline__ void ffma2(u64 &d, u64 a, u64 b) {
    asm("fma.rn.f32x2 %0, %1, %2, %0;" : "+l"(d) : "l"(a), "l"(b));
}
__device__ __forceinline__ u64 dup2(float x) {
    u64 r; asm("mov.b64 %0, {%1, %1};" : "=l"(r) : "f"(x)); return r;
}
__device__ __forceinline__ u64 pack2(float lo, float hi) {
    u64 r; asm("mov.b64 %0, {%1, %2};" : "=l"(r) : "f"(lo), "f"(hi)); return r;
}
__device__ __forceinline__ void unpack2(u64 v, float &lo, float &hi) {
    asm("mov.b64 {%0, %1}, %2;" : "=f"(lo), "=f"(hi) : "l"(v));
}

// ---- mma.sync helpers (HMMA path; compiles at baseline compute_103) ----
__device__ __forceinline__ uint32_t smem_u32(const void* p) {
    uint32_t a; asm("{ .reg .u64 t; cvta.to.shared.u64 t, %1; cvt.u32.u64 %0, t; }" : "=r"(a) : "l"(p));
    return a;
}
__device__ __forceinline__ void mma_bf16(float* c, const uint32_t* a, const uint32_t* b) {
    asm volatile(
        "mma.sync.aligned.m16n8k16.row.col.f32.bf16.bf16.f32 "
        "{%0,%1,%2,%3}, {%4,%5,%6,%7}, {%8,%9}, {%0,%1,%2,%3};"
        : "+f"(c[0]), "+f"(c[1]), "+f"(c[2]), "+f"(c[3])
        : "r"(a[0]), "r"(a[1]), "r"(a[2]), "r"(a[3]), "r"(b[0]), "r"(b[1]));
}
__device__ __forceinline__ void ldsm4(uint32_t* r, uint32_t addr) {
    asm volatile("ldmatrix.sync.aligned.m8n8.x4.shared.b16 {%0,%1,%2,%3}, [%4];"
        : "=r"(r[0]), "=r"(r[1]), "=r"(r[2]), "=r"(r[3]) : "r"(addr));
}
__device__ __forceinline__ void ldsm2(uint32_t* r, uint32_t addr) {
    asm volatile("ldmatrix.sync.aligned.m8n8.x2.shared.b16 {%0,%1}, [%2];"
        : "=r"(r[0]), "=r"(r[1]) : "r"(addr));
}

// ---------------- scratch (device globals) ----------------
static __device__ float g_xp[BATCH*512*NPT];        // in_proj output [b][o][n]
static __device__ float g_xsT[BATCH*NPT*DI];
static __device__ float g_deltaT[BATCH*NPT*DI];
static __device__ float g_Bm[BATCH*NPT*NS];
static __device__ float g_Cm[BATCH*NPT*NS];
static __device__ float g_P[BATCH*NC*NS*DI];
static __device__ float g_H0[BATCH*NC*NS*DI];
static __device__ float g_A[DI*NS];
static __device__ float g_aL[DI*NS];
static __device__ float g_opre[BATCH*NPT*DIMC];
static __device__ __nv_bfloat16 g_whi[512*256];
static __device__ __nv_bfloat16 g_wlo[512*256];
static __device__ __nv_bfloat16 g_wohi[256*256];
static __device__ __nv_bfloat16 g_wolo[256*256];
static __device__ __nv_bfloat16 g_xthi[BATCH*NPT*DIMC];  // [b][n][c]
static __device__ __nv_bfloat16 g_xtlo[BATCH*NPT*DIMC];
static __device__ __nv_bfloat16 g_yhi[BATCH*NPT*DI];     // [b][n][d]
static __device__ __nv_bfloat16 g_ylo[BATCH*NPT*DI];

// ---------------- Kpre ------------------------------------------------------
__global__ void k_pre(const float* __restrict__ A_log) {
    int i = blockIdx.x * 256 + threadIdx.x;
    if (i < DI*NS) {
        float al = A_log[i];
        g_A[i]  = -expf(al);
        g_aL[i] =  expf((float)CL * al);
    }
}

// ---------------- K-wsplit: fp32 -> bf16 hi/lo (generic) --------------------
__global__ void k_wsplit(const float* __restrict__ W, __nv_bfloat16* hi_out,
                         __nv_bfloat16* lo_out, int count) {
    int i = blockIdx.x * 256 + threadIdx.x;
    if (i < count) {
        float v = W[i];
        __nv_bfloat16 hi = __float2bfloat16(v);
        hi_out[i] = hi;
        lo_out[i] = __float2bfloat16(v - __bfloat162float(hi));
    }
}

// ---------------- K-xsplit: x[b][c][n] -> xt hi/lo [b][n][c] bf16 -----------
__global__ void k_xsplit(const float* __restrict__ x) {
    __shared__ float s[32][33];
    int b = blockIdx.z, ct = blockIdx.y, nt = blockIdx.x;
    int c0 = ct*32, n0 = nt*32;
    int tx = threadIdx.x, ty = threadIdx.y;   // 32 x 8
    #pragma unroll
    for (int i = 0; i < 32; i += 8)
        s[ty+i][tx] = x[((size_t)b*DIMC + c0+ty+i)*NPT + n0 + tx];
    __syncthreads();
    #pragma unroll
    for (int i = 0; i < 32; i += 8) {
        float v = s[tx][ty+i];
        __nv_bfloat16 hi = __float2bfloat16(v);
        size_t idx = ((size_t)b*NPT + n0+ty+i)*DIMC + c0 + tx;
        g_xthi[idx] = hi;
        g_xtlo[idx] = __float2bfloat16(v - __bfloat162float(hi));
    }
}

// ---------------- K1: in_proj via mma.sync bf16-split ------------------------
// C[512 x (b,4096)] = W[512x256] * xt[bn x 256]^T. Block 128x128, K=256.
#define SAS 40   // smem row stride in bf16 (conflict-free ldmatrix)
__global__ void __launch_bounds__(256) k_mma_in(const float* __restrict__ bias) {
    __shared__ __align__(16) __nv_bfloat16 sm[4*128*SAS];
    __nv_bfloat16* sAhi = sm;
    __nv_bfloat16* sAlo = sm + 128*SAS;
    __nv_bfloat16* sBhi = sm + 2*128*SAS;
    __nv_bfloat16* sBlo = sm + 3*128*SAS;
    int tid = threadIdx.x, lane = tid & 31, wid = tid >> 5;
    int wm = wid & 1, wn = wid >> 1;          // 2 x 4 warp grid
    int nt = blockIdx.x, mt = blockIdx.y, b = blockIdx.z;
    int o0 = mt*128, n0 = nt*128;

    float acc[4][4][4];
    #pragma unroll
    for (int i = 0; i < 4; i++)
        #pragma unroll
        for (int j = 0; j < 4; j++)
            #pragma unroll
            for (int q = 0; q < 4; q++) acc[i][j][q] = 0.f;

    uint32_t sb = smem_u32(sm);
    uint32_t aBase = sb + (uint32_t)(((wm*64 + (lane&7) + ((lane>>3)&1)*8)*SAS + (lane>>4)*8) * 2);
    uint32_t bBase = sb + 2*128*SAS*2 +
                     (uint32_t)(((wn*32 + (lane&7))*SAS + ((lane>>3)&1)*8) * 2);

    for (int k0 = 0; k0 < 256; k0 += 32) {
        #pragma unroll
        for (int i = 0; i < 2; i++) {
            int idx = tid + i*256;          // 0..511
            int row = idx >> 2, seg = idx & 3;
            size_t ga = (size_t)(o0 + row)*256 + k0 + seg*8;
            *(uint4*)&sAhi[row*SAS + seg*8] = *(const uint4*)&g_whi[ga];
            *(uint4*)&sAlo[row*SAS + seg*8] = *(const uint4*)&g_wlo[ga];
            size_t gb = ((size_t)b*NPT + n0 + row)*DIMC + k0 + seg*8;
            *(uint4*)&sBhi[row*SAS + seg*8] = *(const uint4*)&g_xthi[gb];
            *(uint4*)&sBlo[row*SAS + seg*8] = *(const uint4*)&g_xtlo[gb];
        }
        __syncthreads();
        #pragma unroll
        for (int ks = 0; ks < 2; ks++) {
            uint32_t koff = ks*32;          // bytes: 16 bf16
            uint32_t ah[4][4], al[4][4], bh[4][2], bl[4][2];
            #pragma unroll
            for (int mi = 0; mi < 4; mi++) {
                ldsm4(ah[mi], aBase + mi*(16*SAS*2) + koff);
                ldsm4(al[mi], aBase + 128*SAS*2 + mi*(16*SAS*2) + koff);
            }
            #pragma unroll
            for (int ni = 0; ni < 4; ni++) {
                ldsm2(bh[ni], bBase + ni*(8*SAS*2) + koff);
                ldsm2(bl[ni], bBase + 128*SAS*2 + ni*(8*SAS*2) + koff);
            }
            #pragma unroll
            for (int mi = 0; mi < 4; mi++)
                #pragma unroll
                for (int ni = 0; ni < 4; ni++) {
                    mma_bf16(acc[mi][ni], ah[mi], bh[ni]);
                    mma_bf16(acc[mi][ni], ah[mi], bl[ni]);
                    mma_bf16(acc[mi][ni], al[mi], bh[ni]);
                }
        }
        __syncthreads();
    }
    // epilogue: g_xp[(b*512+o)*NPT + n] + bias[o]
    #pragma unroll
    for (int mi = 0; mi < 4; mi++) {
        int orow = o0 + wm*64 + mi*16 + (lane>>2);
        float bi0 = bias[orow], bi1 = bias[orow+8];
        #pragma unroll
        for (int ni = 0; ni < 4; ni++) {
            int col = n0 + wn*32 + ni*8 + (lane&3)*2;
            float* d0 = &g_xp[((size_t)b*512 + orow)*NPT + col];
            float2 v0 = make_float2(acc[mi][ni][0] + bi0, acc[mi][ni][1] + bi0);
            float2 v1 = make_float2(acc[mi][ni][2] + bi1, acc[mi][ni][3] + bi1);
            *(float2*)d0 = v0;
            *(float2*)(d0 + (size_t)8*NPT) = v1;
        }
    }
}

// ---------------- K6a: out_proj via mma.sync bf16-split ----------------------
// C[bn x 256] = y[bn x 256] * Wo[256x256]^T. Block 128x128, K=256.
__global__ void __launch_bounds__(256) k_mma_out(const float* __restrict__ bout) {
    __shared__ __align__(16) __nv_bfloat16 sm[4*128*SAS];
    __nv_bfloat16* sAhi = sm;
    __nv_bfloat16* sAlo = sm + 128*SAS;
    __nv_bfloat16* sBhi = sm + 2*128*SAS;
    __nv_bfloat16* sBlo = sm + 3*128*SAS;
    int tid = threadIdx.x, lane = tid & 31, wid = tid >> 5;
    int wm = wid & 1, wn = wid >> 1;
    int rt = blockIdx.x, ct = blockIdx.y;
    int r0 = rt*128, c0 = ct*128;

    float acc[4][4][4];
    #pragma unroll
    for (int i = 0; i < 4; i++)
        #pragma unroll
        for (int j = 0; j < 4; j++)
            #pragma unroll
            for (int q = 0; q < 4; q++) acc[i][j][q] = 0.f;

    uint32_t sb = smem_u32(sm);
    uint32_t aBase = sb + (uint32_t)(((wm*64 + (lane&7) + ((lane>>3)&1)*8)*SAS + (lane>>4)*8) * 2);
    uint32_t bBase = sb + 2*128*SAS*2 +
                     (uint32_t)(((wn*32 + (lane&7))*SAS + ((lane>>3)&1)*8) * 2);

    for (int k0 = 0; k0 < 256; k0 += 32) {
        #pragma unroll
        for (int i = 0; i < 2; i++) {
            int idx = tid + i*256;
            int row = idx >> 2, seg = idx & 3;
            size_t ga = (size_t)(r0 + row)*DI + k0 + seg*8;
            *(uint4*)&sAhi[row*SAS + seg*8] = *(const uint4*)&g_yhi[ga];
            *(uint4*)&sAlo[row*SAS + seg*8] = *(const uint4*)&g_ylo[ga];
            size_t gb = (size_t)(c0 + row)*DI + k0 + seg*8;
            *(uint4*)&sBhi[row*SAS + seg*8] = *(const uint4*)&g_wohi[gb];
            *(uint4*)&sBlo[row*SAS + seg*8] = *(const uint4*)&g_wolo[gb];
        }
        __syncthreads();
        #pragma unroll
        for (int ks = 0; ks < 2; ks++) {
            uint32_t koff = ks*32;
            uint32_t ah[4][4], al[4][4], bh[4][2], bl[4][2];
            #pragma unroll
            for (int mi = 0; mi < 4; mi++) {
                ldsm4(ah[mi], aBase + mi*(16*SAS*2) + koff);
                ldsm4(al[mi], aBase + 128*SAS*2 + mi*(16*SAS*2) + koff);
            }
            #pragma unroll
            for (int ni = 0; ni < 4; ni++) {
                ldsm2(bh[ni], bBase + ni*(8*SAS*2) + koff);
                ldsm2(bl[ni], bBase + 128*SAS*2 + ni*(8*SAS*2) + koff);
            }
            #pragma unroll
            for (int mi = 0; mi < 4; mi++)
                #pragma unroll
                for (int ni = 0; ni < 4; ni++) {
                    mma_bf16(acc[mi][ni], ah[mi], bh[ni]);
                    mma_bf16(acc[mi][ni], ah[mi], bl[ni]);
                    mma_bf16(acc[mi][ni], al[mi], bh[ni]);
                }
        }
        __syncthreads();
    }
    // epilogue: g_opre[row*DIMC + c] + bout[c]
    #pragma unroll
    for (int mi = 0; mi < 4; mi++) {
        int row = r0 + wm*64 + mi*16 + (lane>>2);
        #pragma unroll
        for (int ni = 0; ni < 4; ni++) {
            int c = c0 + wn*32 + ni*8 + (lane&3)*2;
            float b0 = bout[c], b1 = bout[c+1];
            float* d0 = &g_opre[(size_t)row*DIMC + c];
            *(float2*)d0 = make_float2(acc[mi][ni][0] + b0, acc[mi][ni][1] + b1);
            *(float2*)(d0 + (size_t)8*DIMC) =
                make_float2(acc[mi][ni][2] + b0, acc[mi][ni][3] + b1);
        }
    }
}

// ---------------- K2a: conv+silu+transpose x1, sigmoid+transpose z ----------
#define CZ_P1 133
#define CZ_P2 129
__global__ void k_convz(const float* __restrict__ wconv, const float* __restrict__ bconv) {
    __shared__ float s1[32*CZ_P1];
    __shared__ float s2[32*CZ_P2];
    int b = blockIdx.z, dt = blockIdx.y, nt = blockIdx.x;
    int d0 = dt*32, n0 = nt*128;
    int tid = threadIdx.x;
    int tx = tid & 31, ty = tid >> 5;
    const float* xpb = g_xp + (size_t)b*512*NPT;

    for (int r = ty; r < 32; r += 8) {
        const float* src = &xpb[(size_t)(d0+r)*NPT + n0 - 3];
        for (int c = tx; c < 131; c += 32) {
            int n = n0 - 3 + c;
            s1[r*CZ_P1 + c] = (n >= 0) ? src[c] : 0.f;
        }
        const float* zsrc = &xpb[(size_t)(256 + d0 + r)*NPT + n0];
        for (int c = tx; c < 128; c += 32)
            s2[r*CZ_P2 + c] = __fdividef(1.f, 1.f + __expf(-zsrc[c]));
    }
    __syncthreads();

    int d = d0 + tx;
    float w0 = wconv[d*4+0], w1 = wconv[d*4+1], w2 = wconv[d*4+2], w3 = wconv[d*4+3];
    float bc = bconv[d];
    float* xdst = g_xsT    + ((size_t)b*NPT + n0)*DI + d;
    float* ddst = g_deltaT + ((size_t)b*NPT + n0)*DI + d;
    const float* r1 = &s1[tx*CZ_P1];
    const float* r2 = &s2[tx*CZ_P2];
    #pragma unroll 4
    for (int n = ty; n < 128; n += 8) {
        float v = fmaf(w3, r1[n+3], fmaf(w2, r1[n+2], fmaf(w1, r1[n+1], fmaf(w0, r1[n], bc))));
        xdst[(size_t)n*DI] = __fdividef(v, 1.f + __expf(-v));
        ddst[(size_t)n*DI] = r2[n];
    }
}

// ---------------- K2b: fused B/C SGEMM, BM=64 -> 256 blocks ------------------
__global__ void k_bcgemm(const float* __restrict__ Bw, const float* __restrict__ Cw) {
    __shared__ float As[32][68];
    __shared__ float Bs[32][32];
    int rt = blockIdx.x;
    int tid = threadIdx.x;
    int tr = tid >> 3;
    int tc = tid & 7;
    u64 acc2[2][2];
    acc2[0][0] = acc2[0][1] = acc2[1][0] = acc2[1][1] = 0ull;

    for (int k0 = 0; k0 < 256; k0 += 32) {
        #pragma unroll
        for (int i = 0; i < 2; i++) {
            int f = tid*2 + i;
            int row = f >> 3, c4 = f & 7;
            float4 v = *(const float4*)&g_xsT[(size_t)(rt*64 + row)*DI + k0 + c4*4];
            As[c4*4+0][row] = v.x; As[c4*4+1][row] = v.y;
            As[c4*4+2][row] = v.z; As[c4*4+3][row] = v.w;
        }
        {
            int col = tid >> 3, c4 = tid & 7;
            const float* wr = (col < 16) ? &Bw[(size_t)col*256] : &Cw[(size_t)(col-16)*256];
            float4 v = *(const float4*)&wr[k0 + c4*4];
            Bs[c4*4+0][col] = v.x; Bs[c4*4+1][col] = v.y;
            Bs[c4*4+2][col] = v.z; Bs[c4*4+3][col] = v.w;
        }
        __syncthreads();
        #pragma unroll
        for (int k = 0; k < 32; k++) {
            u64 a0 = dup2(As[k][tr*2]), a1 = dup2(As[k][tr*2+1]);
            float2 p0 = *(const float2*)&Bs[k][tc*4];
            float2 p1 = *(const float2*)&Bs[k][tc*4+2];
            u64 b0 = pack2(p0.x, p0.y), b1 = pack2(p1.x, p1.y);
            ffma2(acc2[0][0], a0, b0); ffma2(acc2[0][1], a0, b1);
            ffma2(acc2[1][0], a1, b0); ffma2(acc2[1][1], a1, b1);
        }
        __syncthreads();
    }
    float* base = (tc < 4) ? g_Bm : g_Cm;
    int cb = (tc & 3) * 4;
    #pragma unroll
    for (int i = 0; i < 2; i++) {
        size_t row = (size_t)(rt*64 + tr*2 + i);
        float v0, v1, v2, v3;
        unpack2(acc2[i][0], v0, v1);
        unpack2(acc2[i][1], v2, v3);
        base[row*NS + cb + 0] = v0; base[row*NS + cb + 1] = v1;
        base[row*NS + cb + 2] = v2; base[row*NS + cb + 3] = v3;
    }
}

// ---------------- K3 (S1): per-chunk local scan -> P ------------------------
__global__ void k_scan1() {
    __shared__ float sB[CL*NS];
    int b = blockIdx.y, ch = blockIdx.x;
    int tid = threadIdx.x;
    int t0 = ch * CL;
    for (int i = tid; i < CL*NS; i += 256)
        sB[i] = g_Bm[((size_t)b*NPT + t0)*NS + i];
    __syncthreads();
    float A[NS], h[NS];
    #pragma unroll
    for (int s = 0; s < NS; s++) { A[s] = g_A[tid*NS + s]; h[s] = 0.f; }
    const float* dptr = g_deltaT + ((size_t)b*NPT + t0)*DI + tid;
    for (int k = 0; k < CL; k++) {
        float dl = dptr[(size_t)k*DI];
        const float* Bk = &sB[k*NS];
        #pragma unroll
        for (int s = 0; s < NS; s++)
            h[s] = fmaf(A[s], h[s], dl * Bk[s]);
    }
    float* P = g_P + ((size_t)b*NC + ch)*NS*DI + tid;
    #pragma unroll
    for (int s = 0; s < NS; s++) P[s*DI] = h[s];
}

// ---------------- K4 (S2): inter-chunk prefix --------------------------------
__global__ void k_scan2() {
    int g = blockIdx.x * 256 + threadIdx.x;
    int d = g & 255;
    int s = (g >> 8) & 15;
    int b = g >> 12;
    float aL = g_aL[d*NS + s];
    float h = 0.f;
    size_t base = ((size_t)b*NC*NS + s)*DI + d;
    for (int c = 0; c < NC; c++) {
        size_t idx = base + (size_t)c*NS*DI;
        g_H0[idx] = h;
        h = fmaf(aL, h, g_P[idx]);
    }
}

// ---------------- K5 (S3): final scan + y hi/lo bf16 -------------------------
__global__ void k_scan3(const float* __restrict__ Dskip) {
    __shared__ float sB[CL*NS], sC[CL*NS];
    int b = blockIdx.y, ch = blockIdx.x;
    int tid = threadIdx.x;
    int t0 = ch * CL;
    for (int i = tid; i < CL*NS; i += 256) {
        sB[i] = g_Bm[((size_t)b*NPT + t0)*NS + i];
        sC[i] = g_Cm[((size_t)b*NPT + t0)*NS + i];
    }
    __syncthreads();
    float A[NS], h[NS];
    size_t hbase = ((size_t)b*NC + ch)*NS*DI + tid;
    #pragma unroll
    for (int s = 0; s < NS; s++) { A[s] = g_A[tid*NS + s]; h[s] = g_H0[hbase + s*DI]; }
    float dsk = Dskip[tid];
    const float* dptr = g_deltaT + ((size_t)b*NPT + t0)*DI + tid;
    const float* xptr = g_xsT   + ((size_t)b*NPT + t0)*DI + tid;
    __nv_bfloat16* yh = g_yhi + ((size_t)b*NPT + t0)*DI + tid;
    __nv_bfloat16* yl = g_ylo + ((size_t)b*NPT + t0)*DI + tid;
    for (int k = 0; k < CL; k++) {
        float dl = dptr[(size_t)k*DI];
        float xv = xptr[(size_t)k*DI];
        const float* Bk = &sB[k*NS];
        const float* Ck = &sC[k*NS];
        float y = dsk * xv;
        #pragma unroll
        for (int s = 0; s < NS; s++) {
            h[s] = fmaf(A[s], h[s], dl * Bk[s]);
            y = fmaf(h[s], Ck[s], y);
        }
        __nv_bfloat16 hi = __float2bfloat16(y);
        yh[(size_t)k*DI] = hi;
        yl[(size_t)k*DI] = __float2bfloat16(y - __bfloat162float(hi));
    }
}

// ---------------- K6b: residual + LayerNorm + transposed store ---------------
__global__ void k_ln(const float* __restrict__ x,
                     const float* __restrict__ gamma, const float* __restrict__ beta,
                     float* __restrict__ out) {
    __shared__ float s[256][33];
    __shared__ float mu[32], rs[32];
    int b = blockIdx.y, nt = blockIdx.x;
    int n0 = nt * 32;
    int tid = threadIdx.x;
    int wid = tid >> 5, lid = tid & 31;
    for (int i = tid; i < 32*256; i += 256) {
        int n = i >> 8, c = i & 255;
        s[c][n] = g_opre[((size_t)b*NPT + n0 + n)*DIMC + c];
    }
    __syncthreads();
    for (int i = tid; i < 32*256; i += 256) {
        int c = i >> 5, n = i & 31;
        s[c][n] += x[((size_t)b*DIMC + c)*NPT + n0 + n];
    }
    __syncthreads();
    for (int n = wid; n < 32; n += 8) {
        float sum = 0.f, sq = 0.f;
        #pragma unroll
        for (int c = lid; c < 256; c += 32) { float v = s[c][n]; sum += v; sq += v*v; }
        #pragma unroll
        for (int o = 16; o; o >>= 1) {
            sum += __shfl_xor_sync(0xFFFFFFFFu, sum, o);
            sq  += __shfl_xor_sync(0xFFFFFFFFu, sq,  o);
        }
        if (lid == 0) {
            float m = sum * (1.f/256.f);
            mu[n] = m;
            rs[n] = rsqrtf(sq * (1.f/256.f) - m*m + 1e-5f);
        }
    }
    __syncthreads();
    for (int i = tid; i < 32*256; i += 256) {
        int n = i & 31, c = i >> 5;
        float v = (s[c][n] - mu[n]) * rs[n] * gamma[c] + beta[c];
        out[((size_t)b*DIMC + c)*NPT + n0 + n] = v;
    }
}

// ---------------- launch ------------------------------------------------------
extern "C" void kernel_launch(void* const* d_in, const int* in_sizes, int n_in,
                              void* d_out, int out_size) {
    const float* x      = (const float*)d_in[0];
    const float* w_in   = (const float*)d_in[1];
    const float* b_in   = (const float*)d_in[2];
    const float* w_conv = (const float*)d_in[3];
    const float* b_conv = (const float*)d_in[4];
    const float* A_log  = (const float*)d_in[5];
    const float* D_skip = (const float*)d_in[6];
    const float* Bw     = (const float*)d_in[7];
    const float* Cw     = (const float*)d_in[8];
    const float* w_out  = (const float*)d_in[9];
    const float* b_out  = (const float*)d_in[10];
    const float* gamma  = (const float*)d_in[11];
    const float* beta   = (const float*)d_in[12];
    float* out = (float*)d_out;

    __nv_bfloat16 *whi_p, *wlo_p, *wohi_p, *wolo_p;
    cudaGetSymbolAddress((void**)&whi_p,  g_whi);
    cudaGetSymbolAddress((void**)&wlo_p,  g_wlo);
    cudaGetSymbolAddress((void**)&wohi_p, g_wohi);
    cudaGetSymbolAddress((void**)&wolo_p, g_wolo);

    k_pre<<<16, 256>>>(A_log);
    k_wsplit<<<512, 256>>>(w_in,  whi_p,  wlo_p,  512*256);
    k_wsplit<<<256, 256>>>(w_out, wohi_p, wolo_p, 256*256);
    k_xsplit<<<dim3(128, 8, BATCH), dim3(32, 8)>>>(x);
    k_mma_in<<<dim3(32, 4, BATCH), 256>>>(b_in);
    k_convz<<<dim3(32, 8, BATCH), 256>>>(w_conv, b_conv);
    k_bcgemm<<<256, 256>>>(Bw, Cw);
    k_scan1<<<dim3(NC, BATCH), 256>>>();
    k_scan2<<<64, 256>>>();
    k_scan3<<<dim3(NC, BATCH), 256>>>(D_skip);
    k_mma_out<<<dim3(128, 2), 256>>>(b_out);
    k_ln<<<dim3(128, BATCH), 256>>>(x, gamma, beta, out);
}

// round 7
// speedup vs baseline: 2.1770x; 1.0922x over previous
#include <cuda_runtime.h>
#include <cuda_bf16.h>
#include <math.h>
#include <stdint.h>

#define BATCH 4
#define DIMC  256
#define DI    256
#define NS    16
#define NPT   4096
#define NC    64
#define CL    64

typedef unsigned long long u64;

// ---- f32x2 packed-FMA helpers ----
__device__ __forceinline__ void ffma2(u64 &d, u64 a, u64 b) {
    asm("fma.rn.f32x2 %0, %1, %2, %0;" : "+l"(d) : "l"(a), "l"(b));
}
__device__ __forceinline__ u64 dup2(float x) {
    u64 r; asm("mov.b64 %0, {%1, %1};" : "=l"(r) : "f"(x)); return r;
}
__device__ __forceinline__ u64 pack2(float lo, float hi) {
    u64 r; asm("mov.b64 %0, {%1, %2};" : "=l"(r) : "f"(lo), "f"(hi)); return r;
}
__device__ __forceinline__ void unpack2(u64 v, float &lo, float &hi) {
    asm("mov.b64 {%0, %1}, %2;" : "=f"(lo), "=f"(hi) : "l"(v));
}

// ---- mma.sync + cp.async helpers ----
__device__ __forceinline__ uint32_t smem_u32(const void* p) {
    uint32_t a; asm("{ .reg .u64 t; cvta.to.shared.u64 t, %1; cvt.u32.u64 %0, t; }" : "=r"(a) : "l"(p));
    return a;
}
__device__ __forceinline__ void mma_bf16(float* c, const uint32_t* a, const uint32_t* b) {
    asm volatile(
        "mma.sync.aligned.m16n8k16.row.col.f32.bf16.bf16.f32 "
        "{%0,%1,%2,%3}, {%4,%5,%6,%7}, {%8,%9}, {%0,%1,%2,%3};"
        : "+f"(c[0]), "+f"(c[1]), "+f"(c[2]), "+f"(c[3])
        : "r"(a[0]), "r"(a[1]), "r"(a[2]), "r"(a[3]), "r"(b[0]), "r"(b[1]));
}
__device__ __forceinline__ void ldsm4(uint32_t* r, uint32_t addr) {
    asm volatile("ldmatrix.sync.aligned.m8n8.x4.shared.b16 {%0,%1,%2,%3}, [%4];"
        : "=r"(r[0]), "=r"(r[1]), "=r"(r[2]), "=r"(r[3]) : "r"(addr));
}
__device__ __forceinline__ void ldsm2(uint32_t* r, uint32_t addr) {
    asm volatile("ldmatrix.sync.aligned.m8n8.x2.shared.b16 {%0,%1}, [%2];"
        : "=r"(r[0]), "=r"(r[1]) : "r"(addr));
}
__device__ __forceinline__ void cpa16(uint32_t s, const void* g) {
    asm volatile("cp.async.cg.shared.global [%0], [%1], 16;"
        :: "r"(s), "l"(__cvta_generic_to_global(g)));
}
#define CPA_COMMIT() asm volatile("cp.async.commit_group;" ::: "memory")

// ---------------- scratch (device globals) ----------------
static __device__ float g_xp[BATCH*256*NPT];        // in_proj x1 half [b][d][n]
static __device__ float g_xsT[BATCH*NPT*DI];
static __device__ float g_deltaT[BATCH*NPT*DI];
static __device__ float g_Bm[BATCH*NPT*NS];
static __device__ float g_Cm[BATCH*NPT*NS];
static __device__ float g_P[BATCH*NC*NS*DI];
static __device__ float g_H0[BATCH*NC*NS*DI];
static __device__ float g_A[DI*NS];
static __device__ float g_aL[DI*NS];
static __device__ float g_opre[BATCH*NPT*DIMC];
static __device__ __nv_bfloat16 g_whi[512*256];
static __device__ __nv_bfloat16 g_wlo[512*256];
static __device__ __nv_bfloat16 g_wohi[256*256];
static __device__ __nv_bfloat16 g_wolo[256*256];
static __device__ __nv_bfloat16 g_xthi[BATCH*NPT*DIMC];  // [b][n][c]
static __device__ __nv_bfloat16 g_xtlo[BATCH*NPT*DIMC];
static __device__ __nv_bfloat16 g_yhi[BATCH*NPT*DI];     // [b][n][d]
static __device__ __nv_bfloat16 g_ylo[BATCH*NPT*DI];

// ---------------- K-prep: A precompute + W splits + x split/transpose -------
__global__ void k_prep(const float* __restrict__ A_log, const float* __restrict__ w_in,
                       const float* __restrict__ w_out, const float* __restrict__ x) {
    int blk = blockIdx.x, tid = threadIdx.x;
    if (blk < 512) {
        int i = blk*256 + tid;
        float v = w_in[i];
        __nv_bfloat16 hi = __float2bfloat16(v);
        g_whi[i] = hi;
        g_wlo[i] = __float2bfloat16(v - __bfloat162float(hi));
    } else if (blk < 768) {
        int i = (blk-512)*256 + tid;
        float v = w_out[i];
        __nv_bfloat16 hi = __float2bfloat16(v);
        g_wohi[i] = hi;
        g_wolo[i] = __float2bfloat16(v - __bfloat162float(hi));
    } else if (blk < 784) {
        int i = (blk-768)*256 + tid;
        if (i < DI*NS) {
            float al = A_log[i];
            g_A[i]  = -expf(al);
            g_aL[i] =  expf((float)CL * al);
        }
    } else {
        __shared__ float s[32][33];
        int t = blk - 784;
        int b = t >> 10, rem = t & 1023;
        int ct = rem >> 7, nt = rem & 127;
        int c0 = ct*32, n0 = nt*32;
        int tx = tid & 31, ty = tid >> 5;
        #pragma unroll
        for (int i = 0; i < 32; i += 8)
            s[ty+i][tx] = x[((size_t)b*DIMC + c0+ty+i)*NPT + n0 + tx];
        __syncthreads();
        #pragma unroll
        for (int i = 0; i < 32; i += 8) {
            float v = s[tx][ty+i];
            __nv_bfloat16 hi = __float2bfloat16(v);
            size_t idx = ((size_t)b*NPT + n0+ty+i)*DIMC + c0 + tx;
            g_xthi[idx] = hi;
            g_xtlo[idx] = __float2bfloat16(v - __bfloat162float(hi));
        }
    }
}

// ---------------- K1: in_proj mma.sync, cp.async 2-stage pipeline -----------
// mt<2: x1 rows -> g_xp (+bias). mt>=2: z rows -> sigmoid -> transposed g_deltaT.
#define SAS 40
#define ARR_B (128*SAS*2)      // bytes per smem operand array
#define STG_B (4*ARR_B)        // bytes per pipeline stage
#define MMA_DSM (2*STG_B)      // 81920 bytes
__global__ void __launch_bounds__(256) k_mma_in(const float* __restrict__ bias) {
    extern __shared__ char dsm[];
    uint32_t sb = smem_u32(dsm);
    int tid = threadIdx.x, lane = tid & 31, wid = tid >> 5;
    int wm = wid & 1, wn = wid >> 1;
    int nt = blockIdx.x, mt = blockIdx.y, b = blockIdx.z;
    int o0 = mt*128, n0 = nt*128;

    float acc[4][4][4];
    #pragma unroll
    for (int i = 0; i < 4; i++)
        #pragma unroll
        for (int j = 0; j < 4; j++)
            #pragma unroll
            for (int q = 0; q < 4; q++) acc[i][j][q] = 0.f;

    auto issue = [&](int k, int stg) {
        uint32_t sbase = sb + (uint32_t)stg*STG_B;
        int k0 = k*32;
        #pragma unroll
        for (int i = 0; i < 2; i++) {
            int idx = tid + i*256;
            int row = idx >> 2, seg = idx & 3;
            uint32_t so = (uint32_t)((row*SAS + seg*8)*2);
            size_t ga = (size_t)(o0 + row)*256 + k0 + seg*8;
            size_t gb = ((size_t)b*NPT + n0 + row)*DIMC + k0 + seg*8;
            cpa16(sbase + so,             &g_whi[ga]);
            cpa16(sbase + ARR_B + so,     &g_wlo[ga]);
            cpa16(sbase + 2*ARR_B + so,   &g_xthi[gb]);
            cpa16(sbase + 3*ARR_B + so,   &g_xtlo[gb]);
        }
        CPA_COMMIT();
    };

    uint32_t aoff = (uint32_t)(((wm*64 + (lane&7) + ((lane>>3)&1)*8)*SAS + (lane>>4)*8) * 2);
    uint32_t boff = (uint32_t)(((wn*32 + (lane&7))*SAS + ((lane>>3)&1)*8) * 2);

    issue(0, 0);
    issue(1, 1);

    #pragma unroll
    for (int k = 0; k < 8; k++) {
        if (k < 7) asm volatile("cp.async.wait_group 1;" ::: "memory");
        else       asm volatile("cp.async.wait_group 0;" ::: "memory");
        __syncthreads();
        int stg = k & 1;
        uint32_t aBase = sb + (uint32_t)stg*STG_B + aoff;
        uint32_t bBase = sb + (uint32_t)stg*STG_B + 2*ARR_B + boff;
        #pragma unroll
        for (int ks = 0; ks < 2; ks++) {
            uint32_t koff = ks*32;
            uint32_t ah[4][4], al[4][4], bh[4][2], bl[4][2];
            #pragma unroll
            for (int mi = 0; mi < 4; mi++) {
                ldsm4(ah[mi], aBase + mi*(16*SAS*2) + koff);
                ldsm4(al[mi], aBase + ARR_B + mi*(16*SAS*2) + koff);
            }
            #pragma unroll
            for (int ni = 0; ni < 4; ni++) {
                ldsm2(bh[ni], bBase + ni*(8*SAS*2) + koff);
                ldsm2(bl[ni], bBase + ARR_B + ni*(8*SAS*2) + koff);
            }
            #pragma unroll
            for (int mi = 0; mi < 4; mi++)
                #pragma unroll
                for (int ni = 0; ni < 4; ni++) {
                    mma_bf16(acc[mi][ni], ah[mi], bh[ni]);
                    mma_bf16(acc[mi][ni], ah[mi], bl[ni]);
                    mma_bf16(acc[mi][ni], al[mi], bh[ni]);
                }
        }
        __syncthreads();
        if (k + 2 < 8) issue(k + 2, stg);
    }
    __syncthreads();

    if (mt < 2) {
        // x1 half: write g_xp[b][o][n] + bias
        #pragma unroll
        for (int mi = 0; mi < 4; mi++) {
            int orow = o0 + wm*64 + mi*16 + (lane>>2);
            float bi0 = bias[orow], bi1 = bias[orow+8];
            #pragma unroll
            for (int ni = 0; ni < 4; ni++) {
                int col = n0 + wn*32 + ni*8 + (lane&3)*2;
                float* d0 = &g_xp[((size_t)b*256 + orow)*NPT + col];
                *(float2*)d0 = make_float2(acc[mi][ni][0] + bi0, acc[mi][ni][1] + bi0);
                *(float2*)(d0 + (size_t)8*NPT) =
                    make_float2(acc[mi][ni][2] + bi1, acc[mi][ni][3] + bi1);
            }
        }
    } else {
        // z half: sigmoid, transpose via smem, write g_deltaT[b][n][d]
        float* stage = (float*)dsm;   // [128 n][132]
        int d0base = (mt - 2) * 128;
        #pragma unroll
        for (int mi = 0; mi < 4; mi++) {
            int rl = wm*64 + mi*16 + (lane>>2);
            float bi0 = bias[o0 + rl], bi1 = bias[o0 + rl + 8];
            #pragma unroll
            for (int ni = 0; ni < 4; ni++) {
                int cl = wn*32 + ni*8 + (lane&3)*2;
                float v0 = acc[mi][ni][0] + bi0, v1 = acc[mi][ni][1] + bi0;
                float v2 = acc[mi][ni][2] + bi1, v3 = acc[mi][ni][3] + bi1;
                stage[(size_t)cl*132 + rl]         = __fdividef(1.f, 1.f + __expf(-v0));
                stage[(size_t)(cl+1)*132 + rl]     = __fdividef(1.f, 1.f + __expf(-v1));
                stage[(size_t)cl*132 + rl + 8]     = __fdividef(1.f, 1.f + __expf(-v2));
                stage[(size_t)(cl+1)*132 + rl + 8] = __fdividef(1.f, 1.f + __expf(-v3));
            }
        }
        __syncthreads();
        for (int idx = tid; idx < 128*128; idx += 256) {
            int n = idx >> 7, dl = idx & 127;
            g_deltaT[((size_t)b*NPT + n0 + n)*DI + d0base + dl] = stage[(size_t)n*132 + dl];
        }
    }
}

// ---------------- K6a: out_proj mma.sync, cp.async pipeline ------------------
__global__ void __launch_bounds__(256) k_mma_out(const float* __restrict__ bout) {
    extern __shared__ char dsm[];
    uint32_t sb = smem_u32(dsm);
    int tid = threadIdx.x, lane = tid & 31, wid = tid >> 5;
    int wm = wid & 1, wn = wid >> 1;
    int rt = blockIdx.x, ct = blockIdx.y;
    int r0 = rt*128, c0 = ct*128;

    float acc[4][4][4];
    #pragma unroll
    for (int i = 0; i < 4; i++)
        #pragma unroll
        for (int j = 0; j < 4; j++)
            #pragma unroll
            for (int q = 0; q < 4; q++) acc[i][j][q] = 0.f;

    auto issue = [&](int k, int stg) {
        uint32_t sbase = sb + (uint32_t)stg*STG_B;
        int k0 = k*32;
        #pragma unroll
        for (int i = 0; i < 2; i++) {
            int idx = tid + i*256;
            int row = idx >> 2, seg = idx & 3;
            uint32_t so = (uint32_t)((row*SAS + seg*8)*2);
            size_t ga = (size_t)(r0 + row)*DI + k0 + seg*8;
            size_t gb = (size_t)(c0 + row)*DI + k0 + seg*8;
            cpa16(sbase + so,           &g_yhi[ga]);
            cpa16(sbase + ARR_B + so,   &g_ylo[ga]);
            cpa16(sbase + 2*ARR_B + so, &g_wohi[gb]);
            cpa16(sbase + 3*ARR_B + so, &g_wolo[gb]);
        }
        CPA_COMMIT();
    };

    uint32_t aoff = (uint32_t)(((wm*64 + (lane&7) + ((lane>>3)&1)*8)*SAS + (lane>>4)*8) * 2);
    uint32_t boff = (uint32_t)(((wn*32 + (lane&7))*SAS + ((lane>>3)&1)*8) * 2);

    issue(0, 0);
    issue(1, 1);

    #pragma unroll
    for (int k = 0; k < 8; k++) {
        if (k < 7) asm volatile("cp.async.wait_group 1;" ::: "memory");
        else       asm volatile("cp.async.wait_group 0;" ::: "memory");
        __syncthreads();
        int stg = k & 1;
        uint32_t aBase = sb + (uint32_t)stg*STG_B + aoff;
        uint32_t bBase = sb + (uint32_t)stg*STG_B + 2*ARR_B + boff;
        #pragma unroll
        for (int ks = 0; ks < 2; ks++) {
            uint32_t koff = ks*32;
            uint32_t ah[4][4], al[4][4], bh[4][2], bl[4][2];
            #pragma unroll
            for (int mi = 0; mi < 4; mi++) {
                ldsm4(ah[mi], aBase + mi*(16*SAS*2) + koff);
                ldsm4(al[mi], aBase + ARR_B + mi*(16*SAS*2) + koff);
            }
            #pragma unroll
            for (int ni = 0; ni < 4; ni++) {
                ldsm2(bh[ni], bBase + ni*(8*SAS*2) + koff);
                ldsm2(bl[ni], bBase + ARR_B + ni*(8*SAS*2) + koff);
            }
            #pragma unroll
            for (int mi = 0; mi < 4; mi++)
                #pragma unroll
                for (int ni = 0; ni < 4; ni++) {
                    mma_bf16(acc[mi][ni], ah[mi], bh[ni]);
                    mma_bf16(acc[mi][ni], ah[mi], bl[ni]);
                    mma_bf16(acc[mi][ni], al[mi], bh[ni]);
                }
        }
        __syncthreads();
        if (k + 2 < 8) issue(k + 2, stg);
    }

    #pragma unroll
    for (int mi = 0; mi < 4; mi++) {
        int row = r0 + wm*64 + mi*16 + (lane>>2);
        #pragma unroll
        for (int ni = 0; ni < 4; ni++) {
            int c = c0 + wn*32 + ni*8 + (lane&3)*2;
            float b0 = bout[c], b1 = bout[c+1];
            float* d0 = &g_opre[(size_t)row*DIMC + c];
            *(float2*)d0 = make_float2(acc[mi][ni][0] + b0, acc[mi][ni][1] + b1);
            *(float2*)(d0 + (size_t)8*DIMC) =
                make_float2(acc[mi][ni][2] + b0, acc[mi][ni][3] + b1);
        }
    }
}

// ---------------- K2a: conv+silu+transpose x1 (z handled in mma_in) ---------
#define CZ_P1 133
__global__ void k_convz(const float* __restrict__ wconv, const float* __restrict__ bconv) {
    __shared__ float s1[32*CZ_P1];
    int b = blockIdx.z, dt = blockIdx.y, nt = blockIdx.x;
    int d0 = dt*32, n0 = nt*128;
    int tid = threadIdx.x;
    int tx = tid & 31, ty = tid >> 5;
    const float* xpb = g_xp + (size_t)b*256*NPT;

    for (int r = ty; r < 32; r += 8) {
        const float* src = &xpb[(size_t)(d0+r)*NPT + n0 - 3];
        for (int c = tx; c < 131; c += 32) {
            int n = n0 - 3 + c;
            s1[r*CZ_P1 + c] = (n >= 0) ? src[c] : 0.f;
        }
    }
    __syncthreads();

    int d = d0 + tx;
    float w0 = wconv[d*4+0], w1 = wconv[d*4+1], w2 = wconv[d*4+2], w3 = wconv[d*4+3];
    float bc = bconv[d];
    float* xdst = g_xsT + ((size_t)b*NPT + n0)*DI + d;
    const float* r1 = &s1[tx*CZ_P1];
    #pragma unroll 4
    for (int n = ty; n < 128; n += 8) {
        float v = fmaf(w3, r1[n+3], fmaf(w2, r1[n+2], fmaf(w1, r1[n+1], fmaf(w0, r1[n], bc))));
        xdst[(size_t)n*DI] = __fdividef(v, 1.f + __expf(-v));
    }
}

// ---------------- K2b: fused B/C SGEMM, BM=64 --------------------------------
__global__ void k_bcgemm(const float* __restrict__ Bw, const float* __restrict__ Cw) {
    __shared__ float As[32][68];
    __shared__ float Bs[32][32];
    int rt = blockIdx.x;
    int tid = threadIdx.x;
    int tr = tid >> 3;
    int tc = tid & 7;
    u64 acc2[2][2];
    acc2[0][0] = acc2[0][1] = acc2[1][0] = acc2[1][1] = 0ull;

    for (int k0 = 0; k0 < 256; k0 += 32) {
        #pragma unroll
        for (int i = 0; i < 2; i++) {
            int f = tid*2 + i;
            int row = f >> 3, c4 = f & 7;
            float4 v = *(const float4*)&g_xsT[(size_t)(rt*64 + row)*DI + k0 + c4*4];
            As[c4*4+0][row] = v.x; As[c4*4+1][row] = v.y;
            As[c4*4+2][row] = v.z; As[c4*4+3][row] = v.w;
        }
        {
            int col = tid >> 3, c4 = tid & 7;
            const float* wr = (col < 16) ? &Bw[(size_t)col*256] : &Cw[(size_t)(col-16)*256];
            float4 v = *(const float4*)&wr[k0 + c4*4];
            Bs[c4*4+0][col] = v.x; Bs[c4*4+1][col] = v.y;
            Bs[c4*4+2][col] = v.z; Bs[c4*4+3][col] = v.w;
        }
        __syncthreads();
        #pragma unroll
        for (int k = 0; k < 32; k++) {
            u64 a0 = dup2(As[k][tr*2]), a1 = dup2(As[k][tr*2+1]);
            float2 p0 = *(const float2*)&Bs[k][tc*4];
            float2 p1 = *(const float2*)&Bs[k][tc*4+2];
            u64 b0 = pack2(p0.x, p0.y), b1 = pack2(p1.x, p1.y);
            ffma2(acc2[0][0], a0, b0); ffma2(acc2[0][1], a0, b1);
            ffma2(acc2[1][0], a1, b0); ffma2(acc2[1][1], a1, b1);
        }
        __syncthreads();
    }
    float* base = (tc < 4) ? g_Bm : g_Cm;
    int cb = (tc & 3) * 4;
    #pragma unroll
    for (int i = 0; i < 2; i++) {
        size_t row = (size_t)(rt*64 + tr*2 + i);
        float v0, v1, v2, v3;
        unpack2(acc2[i][0], v0, v1);
        unpack2(acc2[i][1], v2, v3);
        base[row*NS + cb + 0] = v0; base[row*NS + cb + 1] = v1;
        base[row*NS + cb + 2] = v2; base[row*NS + cb + 3] = v3;
    }
}

// ---------------- K3 (S1): per-chunk local scan -> P ------------------------
__global__ void k_scan1() {
    __shared__ float sB[CL*NS];
    int b = blockIdx.y, ch = blockIdx.x;
    int tid = threadIdx.x;
    int t0 = ch * CL;
    for (int i = tid; i < CL*NS; i += 256)
        sB[i] = g_Bm[((size_t)b*NPT + t0)*NS + i];
    __syncthreads();
    float A[NS], h[NS];
    #pragma unroll
    for (int s = 0; s < NS; s++) { A[s] = g_A[tid*NS + s]; h[s] = 0.f; }
    const float* dptr = g_deltaT + ((size_t)b*NPT + t0)*DI + tid;
    for (int k = 0; k < CL; k++) {
        float dl = dptr[(size_t)k*DI];
        const float* Bk = &sB[k*NS];
        #pragma unroll
        for (int s = 0; s < NS; s++)
            h[s] = fmaf(A[s], h[s], dl * Bk[s]);
    }
    float* P = g_P + ((size_t)b*NC + ch)*NS*DI + tid;
    #pragma unroll
    for (int s = 0; s < NS; s++) P[s*DI] = h[s];
}

// ---------------- K4 (S2): inter-chunk prefix --------------------------------
__global__ void k_scan2() {
    int g = blockIdx.x * 256 + threadIdx.x;
    int d = g & 255;
    int s = (g >> 8) & 15;
    int b = g >> 12;
    float aL = g_aL[d*NS + s];
    float h = 0.f;
    size_t base = ((size_t)b*NC*NS + s)*DI + d;
    for (int c = 0; c < NC; c++) {
        size_t idx = base + (size_t)c*NS*DI;
        g_H0[idx] = h;
        h = fmaf(aL, h, g_P[idx]);
    }
}

// ---------------- K5 (S3): final scan + y hi/lo bf16 -------------------------
__global__ void k_scan3(const float* __restrict__ Dskip) {
    __shared__ float sB[CL*NS], sC[CL*NS];
    int b = blockIdx.y, ch = blockIdx.x;
    int tid = threadIdx.x;
    int t0 = ch * CL;
    for (int i = tid; i < CL*NS; i += 256) {
        sB[i] = g_Bm[((size_t)b*NPT + t0)*NS + i];
        sC[i] = g_Cm[((size_t)b*NPT + t0)*NS + i];
    }
    __syncthreads();
    float A[NS], h[NS];
    size_t hbase = ((size_t)b*NC + ch)*NS*DI + tid;
    #pragma unroll
    for (int s = 0; s < NS; s++) { A[s] = g_A[tid*NS + s]; h[s] = g_H0[hbase + s*DI]; }
    float dsk = Dskip[tid];
    const float* dptr = g_deltaT + ((size_t)b*NPT + t0)*DI + tid;
    const float* xptr = g_xsT   + ((size_t)b*NPT + t0)*DI + tid;
    __nv_bfloat16* yh = g_yhi + ((size_t)b*NPT + t0)*DI + tid;
    __nv_bfloat16* yl = g_ylo + ((size_t)b*NPT + t0)*DI + tid;
    for (int k = 0; k < CL; k++) {
        float dl = dptr[(size_t)k*DI];
        float xv = xptr[(size_t)k*DI];
        const float* Bk = &sB[k*NS];
        const float* Ck = &sC[k*NS];
        float y = dsk * xv;
        #pragma unroll
        for (int s = 0; s < NS; s++) {
            h[s] = fmaf(A[s], h[s], dl * Bk[s]);
            y = fmaf(h[s], Ck[s], y);
        }
        __nv_bfloat16 hi = __float2bfloat16(y);
        yh[(size_t)k*DI] = hi;
        yl[(size_t)k*DI] = __float2bfloat16(y - __bfloat162float(hi));
    }
}

// ---------------- K6b: residual + LayerNorm + transposed store ---------------
__global__ void k_ln(const float* __restrict__ x,
                     const float* __restrict__ gamma, const float* __restrict__ beta,
                     float* __restrict__ out) {
    __shared__ float s[256][33];
    __shared__ float mu[32], rs[32];
    int b = blockIdx.y, nt = blockIdx.x;
    int n0 = nt * 32;
    int tid = threadIdx.x;
    int wid = tid >> 5, lid = tid & 31;
    for (int i = tid; i < 32*256; i += 256) {
        int n = i >> 8, c = i & 255;
        s[c][n] = g_opre[((size_t)b*NPT + n0 + n)*DIMC + c];
    }
    __syncthreads();
    for (int i = tid; i < 32*256; i += 256) {
        int c = i >> 5, n = i & 31;
        s[c][n] += x[((size_t)b*DIMC + c)*NPT + n0 + n];
    }
    __syncthreads();
    for (int n = wid; n < 32; n += 8) {
        float sum = 0.f, sq = 0.f;
        #pragma unroll
        for (int c = lid; c < 256; c += 32) { float v = s[c][n]; sum += v; sq += v*v; }
        #pragma unroll
        for (int o = 16; o; o >>= 1) {
            sum += __shfl_xor_sync(0xFFFFFFFFu, sum, o);
            sq  += __shfl_xor_sync(0xFFFFFFFFu, sq,  o);
        }
        if (lid == 0) {
            float m = sum * (1.f/256.f);
            mu[n] = m;
            rs[n] = rsqrtf(sq * (1.f/256.f) - m*m + 1e-5f);
        }
    }
    __syncthreads();
    for (int i = tid; i < 32*256; i += 256) {
        int n = i & 31, c = i >> 5;
        float v = (s[c][n] - mu[n]) * rs[n] * gamma[c] + beta[c];
        out[((size_t)b*DIMC + c)*NPT + n0 + n] = v;
    }
}

// ---------------- launch ------------------------------------------------------
extern "C" void kernel_launch(void* const* d_in, const int* in_sizes, int n_in,
                              void* d_out, int out_size) {
    const float* x      = (const float*)d_in[0];
    const float* w_in   = (const float*)d_in[1];
    const float* b_in   = (const float*)d_in[2];
    const float* w_conv = (const float*)d_in[3];
    const float* b_conv = (const float*)d_in[4];
    const float* A_log  = (const float*)d_in[5];
    const float* D_skip = (const float*)d_in[6];
    const float* Bw     = (const float*)d_in[7];
    const float* Cw     = (const float*)d_in[8];
    const float* w_out  = (const float*)d_in[9];
    const float* b_out  = (const float*)d_in[10];
    const float* gamma  = (const float*)d_in[11];
    const float* beta   = (const float*)d_in[12];
    float* out = (float*)d_out;

    cudaFuncSetAttribute(k_mma_in,  cudaFuncAttributeMaxDynamicSharedMemorySize, MMA_DSM);
    cudaFuncSetAttribute(k_mma_out, cudaFuncAttributeMaxDynamicSharedMemorySize, MMA_DSM);

    k_prep<<<784 + 4096, 256>>>(A_log, w_in, w_out, x);
    k_mma_in<<<dim3(32, 4, BATCH), 256, MMA_DSM>>>(b_in);
    k_convz<<<dim3(32, 8, BATCH), 256>>>(w_conv, b_conv);
    k_bcgemm<<<256, 256>>>(Bw, Cw);
    k_scan1<<<dim3(NC, BATCH), 256>>>();
    k_scan2<<<64, 256>>>();
    k_scan3<<<dim3(NC, BATCH), 256>>>(D_skip);
    k_mma_out<<<dim3(128, 2), 256, MMA_DSM>>>(b_out);
    k_ln<<<dim3(128, BATCH), 256>>>(x, gamma, beta, out);
}

// round 8
// speedup vs baseline: 2.1960x; 1.0087x over previous
#include <cuda_runtime.h>
#include <cuda_bf16.h>
#include <math.h>
#include <stdint.h>

#define BATCH 4
#define DIMC  256
#define DI    256
#define NS    16
#define NPT   4096
#define NC    128
#define CL    32

typedef unsigned long long u64;

// ---- mma.sync + cp.async helpers ----
__device__ __forceinline__ uint32_t smem_u32(const void* p) {
    uint32_t a; asm("{ .reg .u64 t; cvta.to.shared.u64 t, %1; cvt.u32.u64 %0, t; }" : "=r"(a) : "l"(p));
    return a;
}
__device__ __forceinline__ void mma_bf16(float* c, const uint32_t* a, const uint32_t* b) {
    asm volatile(
        "mma.sync.aligned.m16n8k16.row.col.f32.bf16.bf16.f32 "
        "{%0,%1,%2,%3}, {%4,%5,%6,%7}, {%8,%9}, {%0,%1,%2,%3};"
        : "+f"(c[0]), "+f"(c[1]), "+f"(c[2]), "+f"(c[3])
        : "r"(a[0]), "r"(a[1]), "r"(a[2]), "r"(a[3]), "r"(b[0]), "r"(b[1]));
}
__device__ __forceinline__ void ldsm4(uint32_t* r, uint32_t addr) {
    asm volatile("ldmatrix.sync.aligned.m8n8.x4.shared.b16 {%0,%1,%2,%3}, [%4];"
        : "=r"(r[0]), "=r"(r[1]), "=r"(r[2]), "=r"(r[3]) : "r"(addr));
}
__device__ __forceinline__ void ldsm2(uint32_t* r, uint32_t addr) {
    asm volatile("ldmatrix.sync.aligned.m8n8.x2.shared.b16 {%0,%1}, [%2];"
        : "=r"(r[0]), "=r"(r[1]) : "r"(addr));
}
__device__ __forceinline__ void cpa16(uint32_t s, const void* g) {
    asm volatile("cp.async.cg.shared.global [%0], [%1], 16;"
        :: "r"(s), "l"(__cvta_generic_to_global(g)));
}
#define CPA_COMMIT() asm volatile("cp.async.commit_group;" ::: "memory")

// ---------------- scratch (device globals) ----------------
static __device__ float g_xp[BATCH*256*NPT];        // in_proj x1 half [b][d][n]
static __device__ float g_deltaT[BATCH*NPT*DI];
static __device__ float g_Bm[BATCH*NPT*NS];
static __device__ float g_Cm[BATCH*NPT*NS];
static __device__ float g_P[BATCH*NC*NS*DI];
static __device__ float g_H0[BATCH*NC*NS*DI];
static __device__ float g_A[DI*NS];
static __device__ float g_aL[DI*NS];
static __device__ float g_opre[BATCH*NPT*DIMC];
static __device__ __nv_bfloat16 g_whi[512*256];
static __device__ __nv_bfloat16 g_wlo[512*256];
static __device__ __nv_bfloat16 g_wohi[256*256];
static __device__ __nv_bfloat16 g_wolo[256*256];
static __device__ __nv_bfloat16 g_wbchi[32*256];    // [Bw;Cw] hi
static __device__ __nv_bfloat16 g_wbclo[32*256];
static __device__ __nv_bfloat16 g_xthi[BATCH*NPT*DIMC];  // [b][n][c]
static __device__ __nv_bfloat16 g_xtlo[BATCH*NPT*DIMC];
static __device__ __nv_bfloat16 g_xshi[BATCH*NPT*DI];    // silu(conv) hi [b][n][d]
static __device__ __nv_bfloat16 g_xslo[BATCH*NPT*DI];
static __device__ __nv_bfloat16 g_yhi[BATCH*NPT*DI];     // [b][n][d]
static __device__ __nv_bfloat16 g_ylo[BATCH*NPT*DI];

// ---------------- K-prep: A precompute + all weight splits + x split --------
__global__ void k_prep(const float* __restrict__ A_log, const float* __restrict__ w_in,
                       const float* __restrict__ w_out, const float* __restrict__ Bw,
                       const float* __restrict__ Cw, const float* __restrict__ x) {
    int blk = blockIdx.x, tid = threadIdx.x;
    if (blk < 512) {
        int i = blk*256 + tid;
        float v = w_in[i];
        __nv_bfloat16 hi = __float2bfloat16(v);
        g_whi[i] = hi;
        g_wlo[i] = __float2bfloat16(v - __bfloat162float(hi));
    } else if (blk < 768) {
        int i = (blk-512)*256 + tid;
        float v = w_out[i];
        __nv_bfloat16 hi = __float2bfloat16(v);
        g_wohi[i] = hi;
        g_wolo[i] = __float2bfloat16(v - __bfloat162float(hi));
    } else if (blk < 784) {
        int i = (blk-768)*256 + tid;
        if (i < DI*NS) {
            float al = A_log[i];
            g_A[i]  = -expf(al);
            g_aL[i] =  expf((float)CL * al);   // CL even
        }
    } else if (blk < 816) {
        int i = (blk-784)*256 + tid;          // 0..8191
        float v = (i < 4096) ? Bw[i] : Cw[i - 4096];
        __nv_bfloat16 hi = __float2bfloat16(v);
        g_wbchi[i] = hi;
        g_wbclo[i] = __float2bfloat16(v - __bfloat162float(hi));
    } else {
        __shared__ float s[32][33];
        int t = blk - 816;
        int b = t >> 10, rem = t & 1023;
        int ct = rem >> 7, nt = rem & 127;
        int c0 = ct*32, n0 = nt*32;
        int tx = tid & 31, ty = tid >> 5;
        #pragma unroll
        for (int i = 0; i < 32; i += 8)
            s[ty+i][tx] = x[((size_t)b*DIMC + c0+ty+i)*NPT + n0 + tx];
        __syncthreads();
        #pragma unroll
        for (int i = 0; i < 32; i += 8) {
            float v = s[tx][ty+i];
            __nv_bfloat16 hi = __float2bfloat16(v);
            size_t idx = ((size_t)b*NPT + n0+ty+i)*DIMC + c0 + tx;
            g_xthi[idx] = hi;
            g_xtlo[idx] = __float2bfloat16(v - __bfloat162float(hi));
        }
    }
}

// ---------------- K1: in_proj mma.sync, cp.async 2-stage pipeline -----------
#define SAS 40
#define ARR_B (128*SAS*2)
#define STG_B (4*ARR_B)
#define MMA_DSM (2*STG_B)
__global__ void __launch_bounds__(256) k_mma_in(const float* __restrict__ bias) {
    extern __shared__ char dsm[];
    uint32_t sb = smem_u32(dsm);
    int tid = threadIdx.x, lane = tid & 31, wid = tid >> 5;
    int wm = wid & 1, wn = wid >> 1;
    int nt = blockIdx.x, mt = blockIdx.y, b = blockIdx.z;
    int o0 = mt*128, n0 = nt*128;

    float acc[4][4][4];
    #pragma unroll
    for (int i = 0; i < 4; i++)
        #pragma unroll
        for (int j = 0; j < 4; j++)
            #pragma unroll
            for (int q = 0; q < 4; q++) acc[i][j][q] = 0.f;

    auto issue = [&](int k, int stg) {
        uint32_t sbase = sb + (uint32_t)stg*STG_B;
        int k0 = k*32;
        #pragma unroll
        for (int i = 0; i < 2; i++) {
            int idx = tid + i*256;
            int row = idx >> 2, seg = idx & 3;
            uint32_t so = (uint32_t)((row*SAS + seg*8)*2);
            size_t ga = (size_t)(o0 + row)*256 + k0 + seg*8;
            size_t gb = ((size_t)b*NPT + n0 + row)*DIMC + k0 + seg*8;
            cpa16(sbase + so,             &g_whi[ga]);
            cpa16(sbase + ARR_B + so,     &g_wlo[ga]);
            cpa16(sbase + 2*ARR_B + so,   &g_xthi[gb]);
            cpa16(sbase + 3*ARR_B + so,   &g_xtlo[gb]);
        }
        CPA_COMMIT();
    };

    uint32_t aoff = (uint32_t)(((wm*64 + (lane&15))*SAS + (lane>>4)*8) * 2);
    uint32_t boff = (uint32_t)(((wn*32 + (lane&7))*SAS + ((lane>>3)&1)*8) * 2);

    issue(0, 0);
    issue(1, 1);

    #pragma unroll
    for (int k = 0; k < 8; k++) {
        if (k < 7) asm volatile("cp.async.wait_group 1;" ::: "memory");
        else       asm volatile("cp.async.wait_group 0;" ::: "memory");
        __syncthreads();
        int stg = k & 1;
        uint32_t aBase = sb + (uint32_t)stg*STG_B + aoff;
        uint32_t bBase = sb + (uint32_t)stg*STG_B + 2*ARR_B + boff;
        #pragma unroll
        for (int ks = 0; ks < 2; ks++) {
            uint32_t koff = ks*32;
            uint32_t ah[4][4], al[4][4], bh[4][2], bl[4][2];
            #pragma unroll
            for (int mi = 0; mi < 4; mi++) {
                ldsm4(ah[mi], aBase + mi*(16*SAS*2) + koff);
                ldsm4(al[mi], aBase + ARR_B + mi*(16*SAS*2) + koff);
            }
            #pragma unroll
            for (int ni = 0; ni < 4; ni++) {
                ldsm2(bh[ni], bBase + ni*(8*SAS*2) + koff);
                ldsm2(bl[ni], bBase + ARR_B + ni*(8*SAS*2) + koff);
            }
            #pragma unroll
            for (int mi = 0; mi < 4; mi++)
                #pragma unroll
                for (int ni = 0; ni < 4; ni++) {
                    mma_bf16(acc[mi][ni], ah[mi], bh[ni]);
                    mma_bf16(acc[mi][ni], ah[mi], bl[ni]);
                    mma_bf16(acc[mi][ni], al[mi], bh[ni]);
                }
        }
        __syncthreads();
        if (k + 2 < 8) issue(k + 2, stg);
    }
    __syncthreads();

    if (mt < 2) {
        #pragma unroll
        for (int mi = 0; mi < 4; mi++) {
            int orow = o0 + wm*64 + mi*16 + (lane>>2);
            float bi0 = bias[orow], bi1 = bias[orow+8];
            #pragma unroll
            for (int ni = 0; ni < 4; ni++) {
                int col = n0 + wn*32 + ni*8 + (lane&3)*2;
                float* d0 = &g_xp[((size_t)b*256 + orow)*NPT + col];
                *(float2*)d0 = make_float2(acc[mi][ni][0] + bi0, acc[mi][ni][1] + bi0);
                *(float2*)(d0 + (size_t)8*NPT) =
                    make_float2(acc[mi][ni][2] + bi1, acc[mi][ni][3] + bi1);
            }
        }
    } else {
        float* stage = (float*)dsm;
        int d0base = (mt - 2) * 128;
        #pragma unroll
        for (int mi = 0; mi < 4; mi++) {
            int rl = wm*64 + mi*16 + (lane>>2);
            float bi0 = bias[o0 + rl], bi1 = bias[o0 + rl + 8];
            #pragma unroll
            for (int ni = 0; ni < 4; ni++) {
                int cl = wn*32 + ni*8 + (lane&3)*2;
                float v0 = acc[mi][ni][0] + bi0, v1 = acc[mi][ni][1] + bi0;
                float v2 = acc[mi][ni][2] + bi1, v3 = acc[mi][ni][3] + bi1;
                stage[(size_t)cl*132 + rl]         = __fdividef(1.f, 1.f + __expf(-v0));
                stage[(size_t)(cl+1)*132 + rl]     = __fdividef(1.f, 1.f + __expf(-v1));
                stage[(size_t)cl*132 + rl + 8]     = __fdividef(1.f, 1.f + __expf(-v2));
                stage[(size_t)(cl+1)*132 + rl + 8] = __fdividef(1.f, 1.f + __expf(-v3));
            }
        }
        __syncthreads();
        for (int idx = tid; idx < 128*128; idx += 256) {
            int n = idx >> 7, dl = idx & 127;
            g_deltaT[((size_t)b*NPT + n0 + n)*DI + d0base + dl] = stage[(size_t)n*132 + dl];
        }
    }
}

// ---------------- K6a: out_proj mma.sync, cp.async pipeline ------------------
__global__ void __launch_bounds__(256) k_mma_out(const float* __restrict__ bout) {
    extern __shared__ char dsm[];
    uint32_t sb = smem_u32(dsm);
    int tid = threadIdx.x, lane = tid & 31, wid = tid >> 5;
    int wm = wid & 1, wn = wid >> 1;
    int rt = blockIdx.x, ct = blockIdx.y;
    int r0 = rt*128, c0 = ct*128;

    float acc[4][4][4];
    #pragma unroll
    for (int i = 0; i < 4; i++)
        #pragma unroll
        for (int j = 0; j < 4; j++)
            #pragma unroll
            for (int q = 0; q < 4; q++) acc[i][j][q] = 0.f;

    auto issue = [&](int k, int stg) {
        uint32_t sbase = sb + (uint32_t)stg*STG_B;
        int k0 = k*32;
        #pragma unroll
        for (int i = 0; i < 2; i++) {
            int idx = tid + i*256;
            int row = idx >> 2, seg = idx & 3;
            uint32_t so = (uint32_t)((row*SAS + seg*8)*2);
            size_t ga = (size_t)(r0 + row)*DI + k0 + seg*8;
            size_t gb = (size_t)(c0 + row)*DI + k0 + seg*8;
            cpa16(sbase + so,           &g_yhi[ga]);
            cpa16(sbase + ARR_B + so,   &g_ylo[ga]);
            cpa16(sbase + 2*ARR_B + so, &g_wohi[gb]);
            cpa16(sbase + 3*ARR_B + so, &g_wolo[gb]);
        }
        CPA_COMMIT();
    };

    uint32_t aoff = (uint32_t)(((wm*64 + (lane&15))*SAS + (lane>>4)*8) * 2);
    uint32_t boff = (uint32_t)(((wn*32 + (lane&7))*SAS + ((lane>>3)&1)*8) * 2);

    issue(0, 0);
    issue(1, 1);

    #pragma unroll
    for (int k = 0; k < 8; k++) {
        if (k < 7) asm volatile("cp.async.wait_group 1;" ::: "memory");
        else       asm volatile("cp.async.wait_group 0;" ::: "memory");
        __syncthreads();
        int stg = k & 1;
        uint32_t aBase = sb + (uint32_t)stg*STG_B + aoff;
        uint32_t bBase = sb + (uint32_t)stg*STG_B + 2*ARR_B + boff;
        #pragma unroll
        for (int ks = 0; ks < 2; ks++) {
            uint32_t koff = ks*32;
            uint32_t ah[4][4], al[4][4], bh[4][2], bl[4][2];
            #pragma unroll
            for (int mi = 0; mi < 4; mi++) {
                ldsm4(ah[mi], aBase + mi*(16*SAS*2) + koff);
                ldsm4(al[mi], aBase + ARR_B + mi*(16*SAS*2) + koff);
            }
            #pragma unroll
            for (int ni = 0; ni < 4; ni++) {
                ldsm2(bh[ni], bBase + ni*(8*SAS*2) + koff);
                ldsm2(bl[ni], bBase + ARR_B + ni*(8*SAS*2) + koff);
            }
            #pragma unroll
            for (int mi = 0; mi < 4; mi++)
                #pragma unroll
                for (int ni = 0; ni < 4; ni++) {
                    mma_bf16(acc[mi][ni], ah[mi], bh[ni]);
                    mma_bf16(acc[mi][ni], ah[mi], bl[ni]);
                    mma_bf16(acc[mi][ni], al[mi], bh[ni]);
                }
        }
        __syncthreads();
        if (k + 2 < 8) issue(k + 2, stg);
    }

    #pragma unroll
    for (int mi = 0; mi < 4; mi++) {
        int row = r0 + wm*64 + mi*16 + (lane>>2);
        #pragma unroll
        for (int ni = 0; ni < 4; ni++) {
            int c = c0 + wn*32 + ni*8 + (lane&3)*2;
            float b0 = bout[c], b1 = bout[c+1];
            float* d0 = &g_opre[(size_t)row*DIMC + c];
            *(float2*)d0 = make_float2(acc[mi][ni][0] + b0, acc[mi][ni][1] + b1);
            *(float2*)(d0 + (size_t)8*DIMC) =
                make_float2(acc[mi][ni][2] + b0, acc[mi][ni][3] + b1);
        }
    }
}

// ---------------- K2a: conv+silu -> xs hi/lo bf16 transposed ----------------
#define CZ_P1 133
__global__ void k_convz(const float* __restrict__ wconv, const float* __restrict__ bconv) {
    __shared__ float s1[32*CZ_P1];
    int b = blockIdx.z, dt = blockIdx.y, nt = blockIdx.x;
    int d0 = dt*32, n0 = nt*128;
    int tid = threadIdx.x;
    int tx = tid & 31, ty = tid >> 5;
    const float* xpb = g_xp + (size_t)b*256*NPT;

    for (int r = ty; r < 32; r += 8) {
        const float* src = &xpb[(size_t)(d0+r)*NPT + n0 - 3];
        for (int c = tx; c < 131; c += 32) {
            int n = n0 - 3 + c;
            s1[r*CZ_P1 + c] = (n >= 0) ? src[c] : 0.f;
        }
    }
    __syncthreads();

    int d = d0 + tx;
    float w0 = wconv[d*4+0], w1 = wconv[d*4+1], w2 = wconv[d*4+2], w3 = wconv[d*4+3];
    float bc = bconv[d];
    __nv_bfloat16* xh = g_xshi + ((size_t)b*NPT + n0)*DI + d;
    __nv_bfloat16* xl = g_xslo + ((size_t)b*NPT + n0)*DI + d;
    const float* r1 = &s1[tx*CZ_P1];
    #pragma unroll 4
    for (int n = ty; n < 128; n += 8) {
        float v = fmaf(w3, r1[n+3], fmaf(w2, r1[n+2], fmaf(w1, r1[n+1], fmaf(w0, r1[n], bc))));
        float sv = __fdividef(v, 1.f + __expf(-v));
        __nv_bfloat16 hi = __float2bfloat16(sv);
        xh[(size_t)n*DI] = hi;
        xl[(size_t)n*DI] = __float2bfloat16(sv - __bfloat162float(hi));
    }
}

// ---------------- K2b: B/C projection via mma.sync (M=16384,N=32,K=256) -----
#define BC_AB (64*SAS*2)           // A array bytes (64 rows)
#define BC_BB (32*SAS*2)           // B array bytes (32 rows)
#define BC_STG (2*BC_AB + 2*BC_BB) // 15360
__global__ void __launch_bounds__(256) k_mma_bc() {
    __shared__ __align__(16) char dsm[2*BC_STG];
    uint32_t sb = smem_u32(dsm);
    int tid = threadIdx.x, lane = tid & 31, wid = tid >> 5;
    int wm = wid & 3, wn = wid >> 2;     // 4 m-groups x 2 n-groups
    size_t r0 = (size_t)blockIdx.x * 64; // global row over flattened (b,n)

    float acc[2][4];
    #pragma unroll
    for (int i = 0; i < 2; i++)
        #pragma unroll
        for (int q = 0; q < 4; q++) acc[i][q] = 0.f;

    auto issue = [&](int k, int stg) {
        uint32_t sbase = sb + (uint32_t)stg*BC_STG;
        int k0 = k*32;
        #pragma unroll
        for (int i = 0; i < 2; i++) {       // A: 512 ops (hi/lo x 64 rows x 4 segs)
            int idx = tid + i*256;
            int arr = idx >> 8, rem = idx & 255;
            int row = rem >> 2, seg = rem & 3;
            uint32_t so = (uint32_t)arr*BC_AB + (uint32_t)((row*SAS + seg*8)*2);
            size_t g = (r0 + row)*DI + k0 + seg*8;
            cpa16(sbase + so, arr ? (const void*)&g_xslo[g] : (const void*)&g_xshi[g]);
        }
        {                                    // B: 256 ops (hi/lo x 32 rows x 4 segs)
            int arr = tid >> 7, rem = tid & 127;
            int row = rem >> 2, seg = rem & 3;
            uint32_t so = 2*BC_AB + (uint32_t)arr*BC_BB + (uint32_t)((row*SAS + seg*8)*2);
            size_t g = (size_t)row*256 + k0 + seg*8;
            cpa16(sbase + so, arr ? (const void*)&g_wbclo[g] : (const void*)&g_wbchi[g]);
        }
        CPA_COMMIT();
    };

    uint32_t aoff = (uint32_t)(((wm*16 + (lane&15))*SAS + (lane>>4)*8) * 2);
    uint32_t boff = 2*BC_AB + (uint32_t)(((wn*16 + (lane&7))*SAS + ((lane>>3)&1)*8) * 2);

    issue(0, 0);
    issue(1, 1);

    #pragma unroll
    for (int k = 0; k < 8; k++) {
        if (k < 7) asm volatile("cp.async.wait_group 1;" ::: "memory");
        else       asm volatile("cp.async.wait_group 0;" ::: "memory");
        __syncthreads();
        int stg = k & 1;
        uint32_t aBase = sb + (uint32_t)stg*BC_STG + aoff;
        uint32_t bBase = sb + (uint32_t)stg*BC_STG + boff;
        #pragma unroll
        for (int ks = 0; ks < 2; ks++) {
            uint32_t koff = ks*32;
            uint32_t ah[4], al[4], bh[2][2], bl[2][2];
            ldsm4(ah, aBase + koff);
            ldsm4(al, aBase + BC_AB + koff);
            #pragma unroll
            for (int ni = 0; ni < 2; ni++) {
                ldsm2(bh[ni], bBase + ni*(8*SAS*2) + koff);
                ldsm2(bl[ni], bBase + BC_BB + ni*(8*SAS*2) + koff);
            }
            #pragma unroll
            for (int ni = 0; ni < 2; ni++) {
                mma_bf16(acc[ni], ah, bh[ni]);
                mma_bf16(acc[ni], ah, bl[ni]);
                mma_bf16(acc[ni], al, bh[ni]);
            }
        }
        __syncthreads();
        if (k + 2 < 8) issue(k + 2, stg);
    }

    #pragma unroll
    for (int ni = 0; ni < 2; ni++) {
        int col = wn*16 + ni*8 + (lane&3)*2;
        float* base = (col < 16) ? g_Bm : g_Cm;
        int cb = col & 15;
        size_t row = r0 + wm*16 + (lane>>2);
        *(float2*)&base[row*NS + cb]     = make_float2(acc[ni][0], acc[ni][1]);
        *(float2*)&base[(row+8)*NS + cb] = make_float2(acc[ni][2], acc[ni][3]);
    }
}

// ---------------- K3 (S1): per-chunk local scan -> P ------------------------
__global__ void k_scan1() {
    __shared__ float sB[CL*NS];
    int b = blockIdx.y, ch = blockIdx.x;
    int tid = threadIdx.x;
    int t0 = ch * CL;
    for (int i = tid; i < CL*NS; i += 256)
        sB[i] = g_Bm[((size_t)b*NPT + t0)*NS + i];
    __syncthreads();
    float A[NS], h[NS];
    #pragma unroll
    for (int s = 0; s < NS; s++) { A[s] = g_A[tid*NS + s]; h[s] = 0.f; }
    const float* dptr = g_deltaT + ((size_t)b*NPT + t0)*DI + tid;
    for (int k = 0; k < CL; k++) {
        float dl = dptr[(size_t)k*DI];
        const float* Bk = &sB[k*NS];
        #pragma unroll
        for (int s = 0; s < NS; s++)
            h[s] = fmaf(A[s], h[s], dl * Bk[s]);
    }
    float* P = g_P + ((size_t)b*NC + ch)*NS*DI + tid;
    #pragma unroll
    for (int s = 0; s < NS; s++) P[s*DI] = h[s];
}

// ---------------- K4 (S2): inter-chunk prefix --------------------------------
__global__ void k_scan2() {
    int g = blockIdx.x * 256 + threadIdx.x;
    int d = g & 255;
    int s = (g >> 8) & 15;
    int b = g >> 12;
    float aL = g_aL[d*NS + s];
    float h = 0.f;
    size_t base = ((size_t)b*NC*NS + s)*DI + d;
    for (int c = 0; c < NC; c++) {
        size_t idx = base + (size_t)c*NS*DI;
        g_H0[idx] = h;
        h = fmaf(aL, h, g_P[idx]);
    }
}

// ---------------- K5 (S3): final scan + y hi/lo bf16 -------------------------
__global__ void k_scan3(const float* __restrict__ Dskip) {
    __shared__ float sB[CL*NS], sC[CL*NS];
    int b = blockIdx.y, ch = blockIdx.x;
    int tid = threadIdx.x;
    int t0 = ch * CL;
    for (int i = tid; i < CL*NS; i += 256) {
        sB[i] = g_Bm[((size_t)b*NPT + t0)*NS + i];
        sC[i] = g_Cm[((size_t)b*NPT + t0)*NS + i];
    }
    __syncthreads();
    float A[NS], h[NS];
    size_t hbase = ((size_t)b*NC + ch)*NS*DI + tid;
    #pragma unroll
    for (int s = 0; s < NS; s++) { A[s] = g_A[tid*NS + s]; h[s] = g_H0[hbase + s*DI]; }
    float dsk = Dskip[tid];
    const float* dptr = g_deltaT + ((size_t)b*NPT + t0)*DI + tid;
    const __nv_bfloat16* xhp = g_xshi + ((size_t)b*NPT + t0)*DI + tid;
    const __nv_bfloat16* xlp = g_xslo + ((size_t)b*NPT + t0)*DI + tid;
    __nv_bfloat16* yh = g_yhi + ((size_t)b*NPT + t0)*DI + tid;
    __nv_bfloat16* yl = g_ylo + ((size_t)b*NPT + t0)*DI + tid;
    for (int k = 0; k < CL; k++) {
        float dl = dptr[(size_t)k*DI];
        float xv = __bfloat162float(xhp[(size_t)k*DI]) + __bfloat162float(xlp[(size_t)k*DI]);
        const float* Bk = &sB[k*NS];
        const float* Ck = &sC[k*NS];
        float y = dsk * xv;
        #pragma unroll
        for (int s = 0; s < NS; s++) {
            h[s] = fmaf(A[s], h[s], dl * Bk[s]);
            y = fmaf(h[s], Ck[s], y);
        }
        __nv_bfloat16 hi = __float2bfloat16(y);
        yh[(size_t)k*DI] = hi;
        yl[(size_t)k*DI] = __float2bfloat16(y - __bfloat162float(hi));
    }
}

// ---------------- K6b: residual + LayerNorm + transposed store ---------------
__global__ void k_ln(const float* __restrict__ x,
                     const float* __restrict__ gamma, const float* __restrict__ beta,
                     float* __restrict__ out) {
    __shared__ float s[256][33];
    __shared__ float mu[32], rs[32];
    int b = blockIdx.y, nt = blockIdx.x;
    int n0 = nt * 32;
    int tid = threadIdx.x;
    int wid = tid >> 5, lid = tid & 31;
    for (int i = tid; i < 32*256; i += 256) {
        int n = i >> 8, c = i & 255;
        s[c][n] = g_opre[((size_t)b*NPT + n0 + n)*DIMC + c];
    }
    __syncthreads();
    for (int i = tid; i < 32*256; i += 256) {
        int c = i >> 5, n = i & 31;
        s[c][n] += x[((size_t)b*DIMC + c)*NPT + n0 + n];
    }
    __syncthreads();
    for (int n = wid; n < 32; n += 8) {
        float sum = 0.f, sq = 0.f;
        #pragma unroll
        for (int c = lid; c < 256; c += 32) { float v = s[c][n]; sum += v; sq += v*v; }
        #pragma unroll
        for (int o = 16; o; o >>= 1) {
            sum += __shfl_xor_sync(0xFFFFFFFFu, sum, o);
            sq  += __shfl_xor_sync(0xFFFFFFFFu, sq,  o);
        }
        if (lid == 0) {
            float m = sum * (1.f/256.f);
            mu[n] = m;
            rs[n] = rsqrtf(sq * (1.f/256.f) - m*m + 1e-5f);
        }
    }
    __syncthreads();
    for (int i = tid; i < 32*256; i += 256) {
        int n = i & 31, c = i >> 5;
        float v = (s[c][n] - mu[n]) * rs[n] * gamma[c] + beta[c];
        out[((size_t)b*DIMC + c)*NPT + n0 + n] = v;
    }
}

// ---------------- launch ------------------------------------------------------
extern "C" void kernel_launch(void* const* d_in, const int* in_sizes, int n_in,
                              void* d_out, int out_size) {
    const float* x      = (const float*)d_in[0];
    const float* w_in   = (const float*)d_in[1];
    const float* b_in   = (const float*)d_in[2];
    const float* w_conv = (const float*)d_in[3];
    const float* b_conv = (const float*)d_in[4];
    const float* A_log  = (const float*)d_in[5];
    const float* D_skip = (const float*)d_in[6];
    const float* Bw     = (const float*)d_in[7];
    const float* Cw     = (const float*)d_in[8];
    const float* w_out  = (const float*)d_in[9];
    const float* b_out  = (const float*)d_in[10];
    const float* gamma  = (const float*)d_in[11];
    const float* beta   = (const float*)d_in[12];
    float* out = (float*)d_out;

    cudaFuncSetAttribute(k_mma_in,  cudaFuncAttributeMaxDynamicSharedMemorySize, MMA_DSM);
    cudaFuncSetAttribute(k_mma_out, cudaFuncAttributeMaxDynamicSharedMemorySize, MMA_DSM);

    k_prep<<<816 + 4096, 256>>>(A_log, w_in, w_out, Bw, Cw, x);
    k_mma_in<<<dim3(32, 4, BATCH), 256, MMA_DSM>>>(b_in);
    k_convz<<<dim3(32, 8, BATCH), 256>>>(w_conv, b_conv);
    k_mma_bc<<<256, 256>>>();
    k_scan1<<<dim3(NC, BATCH), 256>>>();
    k_scan2<<<64, 256>>>();
    k_scan3<<<dim3(NC, BATCH), 256>>>(D_skip);
    k_mma_out<<<dim3(128, 2), 256, MMA_DSM>>>(b_out);
    k_ln<<<dim3(128, BATCH), 256>>>(x, gamma, beta, out);
}

// round 9
// speedup vs baseline: 2.3013x; 1.0480x over previous
#include <cuda_runtime.h>
#include <cuda_bf16.h>
#include <math.h>
#include <stdint.h>

#define BATCH 4
#define DIMC  256
#define DI    256
#define NS    16
#define NPT   4096
#define NC    64
#define CL    64

// ---- mma.sync + cp.async helpers ----
__device__ __forceinline__ uint32_t smem_u32(const void* p) {
    uint32_t a; asm("{ .reg .u64 t; cvta.to.shared.u64 t, %1; cvt.u32.u64 %0, t; }" : "=r"(a) : "l"(p));
    return a;
}
__device__ __forceinline__ void mma_bf16(float* c, const uint32_t* a, const uint32_t* b) {
    asm volatile(
        "mma.sync.aligned.m16n8k16.row.col.f32.bf16.bf16.f32 "
        "{%0,%1,%2,%3}, {%4,%5,%6,%7}, {%8,%9}, {%0,%1,%2,%3};"
        : "+f"(c[0]), "+f"(c[1]), "+f"(c[2]), "+f"(c[3])
        : "r"(a[0]), "r"(a[1]), "r"(a[2]), "r"(a[3]), "r"(b[0]), "r"(b[1]));
}
__device__ __forceinline__ void ldsm4(uint32_t* r, uint32_t addr) {
    asm volatile("ldmatrix.sync.aligned.m8n8.x4.shared.b16 {%0,%1,%2,%3}, [%4];"
        : "=r"(r[0]), "=r"(r[1]), "=r"(r[2]), "=r"(r[3]) : "r"(addr));
}
__device__ __forceinline__ void ldsm2(uint32_t* r, uint32_t addr) {
    asm volatile("ldmatrix.sync.aligned.m8n8.x2.shared.b16 {%0,%1}, [%2];"
        : "=r"(r[0]), "=r"(r[1]) : "r"(addr));
}
__device__ __forceinline__ void cpa16(uint32_t s, const void* g) {
    asm volatile("cp.async.cg.shared.global [%0], [%1], 16;"
        :: "r"(s), "l"(__cvta_generic_to_global(g)));
}
#define CPA_COMMIT() asm volatile("cp.async.commit_group;" ::: "memory")

// ---------------- scratch (device globals) ----------------
static __device__ float g_xp[BATCH*256*NPT];        // in_proj x1 half [b][d][n]
static __device__ float g_deltaT[BATCH*NPT*DI];
static __device__ float g_Bm[BATCH*NPT*NS];
static __device__ float g_Cm[BATCH*NPT*NS];
static __device__ float g_P[BATCH*NC*NS*DI];
static __device__ float g_H0[BATCH*NC*NS*DI];
static __device__ float g_A[DI*NS];
static __device__ float g_aL[DI*NS];
static __device__ __nv_bfloat16 g_whi[512*256];
static __device__ __nv_bfloat16 g_wlo[512*256];
static __device__ __nv_bfloat16 g_wohi[256*256];
static __device__ __nv_bfloat16 g_wolo[256*256];
static __device__ __nv_bfloat16 g_wbchi[32*256];
static __device__ __nv_bfloat16 g_wbclo[32*256];
static __device__ __nv_bfloat16 g_xthi[BATCH*NPT*DIMC];  // [b][n][c]
static __device__ __nv_bfloat16 g_xtlo[BATCH*NPT*DIMC];
static __device__ __nv_bfloat16 g_xshi[BATCH*NPT*DI];    // silu(conv) [b][n][d]
static __device__ __nv_bfloat16 g_xslo[BATCH*NPT*DI];
static __device__ __nv_bfloat16 g_yhi[BATCH*NPT*DI];     // [b][n][d]
static __device__ __nv_bfloat16 g_ylo[BATCH*NPT*DI];

// ---------------- K-prep ------------------------------------------------------
__global__ void k_prep(const float* __restrict__ A_log, const float* __restrict__ w_in,
                       const float* __restrict__ w_out, const float* __restrict__ Bw,
                       const float* __restrict__ Cw, const float* __restrict__ x) {
    int blk = blockIdx.x, tid = threadIdx.x;
    if (blk < 512) {
        int i = blk*256 + tid;
        float v = w_in[i];
        __nv_bfloat16 hi = __float2bfloat16(v);
        g_whi[i] = hi;
        g_wlo[i] = __float2bfloat16(v - __bfloat162float(hi));
    } else if (blk < 768) {
        int i = (blk-512)*256 + tid;
        float v = w_out[i];
        __nv_bfloat16 hi = __float2bfloat16(v);
        g_wohi[i] = hi;
        g_wolo[i] = __float2bfloat16(v - __bfloat162float(hi));
    } else if (blk < 784) {
        int i = (blk-768)*256 + tid;
        if (i < DI*NS) {
            float al = A_log[i];
            g_A[i]  = -expf(al);
            g_aL[i] =  expf((float)CL * al);   // CL even
        }
    } else if (blk < 816) {
        int i = (blk-784)*256 + tid;
        float v = (i < 4096) ? Bw[i] : Cw[i - 4096];
        __nv_bfloat16 hi = __float2bfloat16(v);
        g_wbchi[i] = hi;
        g_wbclo[i] = __float2bfloat16(v - __bfloat162float(hi));
    } else {
        __shared__ float s[32][33];
        int t = blk - 816;
        int b = t >> 10, rem = t & 1023;
        int ct = rem >> 7, nt = rem & 127;
        int c0 = ct*32, n0 = nt*32;
        int tx = tid & 31, ty = tid >> 5;
        #pragma unroll
        for (int i = 0; i < 32; i += 8)
            s[ty+i][tx] = x[((size_t)b*DIMC + c0+ty+i)*NPT + n0 + tx];
        __syncthreads();
        #pragma unroll
        for (int i = 0; i < 32; i += 8) {
            float v = s[tx][ty+i];
            __nv_bfloat16 hi = __float2bfloat16(v);
            size_t idx = ((size_t)b*NPT + n0+ty+i)*DIMC + c0 + tx;
            g_xthi[idx] = hi;
            g_xtlo[idx] = __float2bfloat16(v - __bfloat162float(hi));
        }
    }
}

// ---------------- K1: in_proj mma.sync, cp.async 2-stage pipeline -----------
#define SAS 40
#define ARR_B (128*SAS*2)
#define STG_B (4*ARR_B)
#define MMA_DSM (2*STG_B)
__global__ void __launch_bounds__(256) k_mma_in(const float* __restrict__ bias) {
    extern __shared__ char dsm[];
    uint32_t sb = smem_u32(dsm);
    int tid = threadIdx.x, lane = tid & 31, wid = tid >> 5;
    int wm = wid & 1, wn = wid >> 1;
    int nt = blockIdx.x, mt = blockIdx.y, b = blockIdx.z;
    int o0 = mt*128, n0 = nt*128;

    float acc[4][4][4];
    #pragma unroll
    for (int i = 0; i < 4; i++)
        #pragma unroll
        for (int j = 0; j < 4; j++)
            #pragma unroll
            for (int q = 0; q < 4; q++) acc[i][j][q] = 0.f;

    auto issue = [&](int k, int stg) {
        uint32_t sbase = sb + (uint32_t)stg*STG_B;
        int k0 = k*32;
        #pragma unroll
        for (int i = 0; i < 2; i++) {
            int idx = tid + i*256;
            int row = idx >> 2, seg = idx & 3;
            uint32_t so = (uint32_t)((row*SAS + seg*8)*2);
            size_t ga = (size_t)(o0 + row)*256 + k0 + seg*8;
            size_t gb = ((size_t)b*NPT + n0 + row)*DIMC + k0 + seg*8;
            cpa16(sbase + so,             &g_whi[ga]);
            cpa16(sbase + ARR_B + so,     &g_wlo[ga]);
            cpa16(sbase + 2*ARR_B + so,   &g_xthi[gb]);
            cpa16(sbase + 3*ARR_B + so,   &g_xtlo[gb]);
        }
        CPA_COMMIT();
    };

    uint32_t aoff = (uint32_t)(((wm*64 + (lane&15))*SAS + (lane>>4)*8) * 2);
    uint32_t boff = (uint32_t)(((wn*32 + (lane&7))*SAS + ((lane>>3)&1)*8) * 2);

    issue(0, 0);
    issue(1, 1);

    #pragma unroll
    for (int k = 0; k < 8; k++) {
        if (k < 7) asm volatile("cp.async.wait_group 1;" ::: "memory");
        else       asm volatile("cp.async.wait_group 0;" ::: "memory");
        __syncthreads();
        int stg = k & 1;
        uint32_t aBase = sb + (uint32_t)stg*STG_B + aoff;
        uint32_t bBase = sb + (uint32_t)stg*STG_B + 2*ARR_B + boff;
        #pragma unroll
        for (int ks = 0; ks < 2; ks++) {
            uint32_t koff = ks*32;
            uint32_t ah[4][4], al[4][4], bh[4][2], bl[4][2];
            #pragma unroll
            for (int mi = 0; mi < 4; mi++) {
                ldsm4(ah[mi], aBase + mi*(16*SAS*2) + koff);
                ldsm4(al[mi], aBase + ARR_B + mi*(16*SAS*2) + koff);
            }
            #pragma unroll
            for (int ni = 0; ni < 4; ni++) {
                ldsm2(bh[ni], bBase + ni*(8*SAS*2) + koff);
                ldsm2(bl[ni], bBase + ARR_B + ni*(8*SAS*2) + koff);
            }
            #pragma unroll
            for (int mi = 0; mi < 4; mi++)
                #pragma unroll
                for (int ni = 0; ni < 4; ni++) {
                    mma_bf16(acc[mi][ni], ah[mi], bh[ni]);
                    mma_bf16(acc[mi][ni], ah[mi], bl[ni]);
                    mma_bf16(acc[mi][ni], al[mi], bh[ni]);
                }
        }
        __syncthreads();
        if (k + 2 < 8) issue(k + 2, stg);
    }
    __syncthreads();

    if (mt < 2) {
        #pragma unroll
        for (int mi = 0; mi < 4; mi++) {
            int orow = o0 + wm*64 + mi*16 + (lane>>2);
            float bi0 = bias[orow], bi1 = bias[orow+8];
            #pragma unroll
            for (int ni = 0; ni < 4; ni++) {
                int col = n0 + wn*32 + ni*8 + (lane&3)*2;
                float* d0 = &g_xp[((size_t)b*256 + orow)*NPT + col];
                *(float2*)d0 = make_float2(acc[mi][ni][0] + bi0, acc[mi][ni][1] + bi0);
                *(float2*)(d0 + (size_t)8*NPT) =
                    make_float2(acc[mi][ni][2] + bi1, acc[mi][ni][3] + bi1);
            }
        }
    } else {
        float* stage = (float*)dsm;
        int d0base = (mt - 2) * 128;
        #pragma unroll
        for (int mi = 0; mi < 4; mi++) {
            int rl = wm*64 + mi*16 + (lane>>2);
            float bi0 = bias[o0 + rl], bi1 = bias[o0 + rl + 8];
            #pragma unroll
            for (int ni = 0; ni < 4; ni++) {
                int cl = wn*32 + ni*8 + (lane&3)*2;
                float v0 = acc[mi][ni][0] + bi0, v1 = acc[mi][ni][1] + bi0;
                float v2 = acc[mi][ni][2] + bi1, v3 = acc[mi][ni][3] + bi1;
                stage[(size_t)cl*132 + rl]         = __fdividef(1.f, 1.f + __expf(-v0));
                stage[(size_t)(cl+1)*132 + rl]     = __fdividef(1.f, 1.f + __expf(-v1));
                stage[(size_t)cl*132 + rl + 8]     = __fdividef(1.f, 1.f + __expf(-v2));
                stage[(size_t)(cl+1)*132 + rl + 8] = __fdividef(1.f, 1.f + __expf(-v3));
            }
        }
        __syncthreads();
        for (int idx = tid; idx < 128*128; idx += 256) {
            int n = idx >> 7, dl = idx & 127;
            g_deltaT[((size_t)b*NPT + n0 + n)*DI + d0base + dl] = stage[(size_t)n*132 + dl];
        }
    }
}

// ---------------- K2a: conv+silu -> xs hi/lo bf16 transposed ----------------
#define CZ_P1 133
__global__ void k_convz(const float* __restrict__ wconv, const float* __restrict__ bconv) {
    __shared__ float s1[32*CZ_P1];
    int b = blockIdx.z, dt = blockIdx.y, nt = blockIdx.x;
    int d0 = dt*32, n0 = nt*128;
    int tid = threadIdx.x;
    int tx = tid & 31, ty = tid >> 5;
    const float* xpb = g_xp + (size_t)b*256*NPT;

    for (int r = ty; r < 32; r += 8) {
        const float* src = &xpb[(size_t)(d0+r)*NPT + n0 - 3];
        for (int c = tx; c < 131; c += 32) {
            int n = n0 - 3 + c;
            s1[r*CZ_P1 + c] = (n >= 0) ? src[c] : 0.f;
        }
    }
    __syncthreads();

    int d = d0 + tx;
    float w0 = wconv[d*4+0], w1 = wconv[d*4+1], w2 = wconv[d*4+2], w3 = wconv[d*4+3];
    float bc = bconv[d];
    __nv_bfloat16* xh = g_xshi + ((size_t)b*NPT + n0)*DI + d;
    __nv_bfloat16* xl = g_xslo + ((size_t)b*NPT + n0)*DI + d;
    const float* r1 = &s1[tx*CZ_P1];
    #pragma unroll 4
    for (int n = ty; n < 128; n += 8) {
        float v = fmaf(w3, r1[n+3], fmaf(w2, r1[n+2], fmaf(w1, r1[n+1], fmaf(w0, r1[n], bc))));
        float sv = __fdividef(v, 1.f + __expf(-v));
        __nv_bfloat16 hi = __float2bfloat16(sv);
        xh[(size_t)n*DI] = hi;
        xl[(size_t)n*DI] = __float2bfloat16(sv - __bfloat162float(hi));
    }
}

// ---------------- K2b: B/C projection via mma.sync --------------------------
#define BC_AB (64*SAS*2)
#define BC_BB (32*SAS*2)
#define BC_STG (2*BC_AB + 2*BC_BB)
__global__ void __launch_bounds__(256) k_mma_bc() {
    __shared__ __align__(16) char dsm[2*BC_STG];
    uint32_t sb = smem_u32(dsm);
    int tid = threadIdx.x, lane = tid & 31, wid = tid >> 5;
    int wm = wid & 3, wn = wid >> 2;
    size_t r0 = (size_t)blockIdx.x * 64;

    float acc[2][4];
    #pragma unroll
    for (int i = 0; i < 2; i++)
        #pragma unroll
        for (int q = 0; q < 4; q++) acc[i][q] = 0.f;

    auto issue = [&](int k, int stg) {
        uint32_t sbase = sb + (uint32_t)stg*BC_STG;
        int k0 = k*32;
        #pragma unroll
        for (int i = 0; i < 2; i++) {
            int idx = tid + i*256;
            int arr = idx >> 8, rem = idx & 255;
            int row = rem >> 2, seg = rem & 3;
            uint32_t so = (uint32_t)arr*BC_AB + (uint32_t)((row*SAS + seg*8)*2);
            size_t g = (r0 + row)*DI + k0 + seg*8;
            cpa16(sbase + so, arr ? (const void*)&g_xslo[g] : (const void*)&g_xshi[g]);
        }
        {
            int arr = tid >> 7, rem = tid & 127;
            int row = rem >> 2, seg = rem & 3;
            uint32_t so = 2*BC_AB + (uint32_t)arr*BC_BB + (uint32_t)((row*SAS + seg*8)*2);
            size_t g = (size_t)row*256 + k0 + seg*8;
            cpa16(sbase + so, arr ? (const void*)&g_wbclo[g] : (const void*)&g_wbchi[g]);
        }
        CPA_COMMIT();
    };

    uint32_t aoff = (uint32_t)(((wm*16 + (lane&15))*SAS + (lane>>4)*8) * 2);
    uint32_t boff = 2*BC_AB + (uint32_t)(((wn*16 + (lane&7))*SAS + ((lane>>3)&1)*8) * 2);

    issue(0, 0);
    issue(1, 1);

    #pragma unroll
    for (int k = 0; k < 8; k++) {
        if (k < 7) asm volatile("cp.async.wait_group 1;" ::: "memory");
        else       asm volatile("cp.async.wait_group 0;" ::: "memory");
        __syncthreads();
        int stg = k & 1;
        uint32_t aBase = sb + (uint32_t)stg*BC_STG + aoff;
        uint32_t bBase = sb + (uint32_t)stg*BC_STG + boff;
        #pragma unroll
        for (int ks = 0; ks < 2; ks++) {
            uint32_t koff = ks*32;
            uint32_t ah[4], al[4], bh[2][2], bl[2][2];
            ldsm4(ah, aBase + koff);
            ldsm4(al, aBase + BC_AB + koff);
            #pragma unroll
            for (int ni = 0; ni < 2; ni++) {
                ldsm2(bh[ni], bBase + ni*(8*SAS*2) + koff);
                ldsm2(bl[ni], bBase + BC_BB + ni*(8*SAS*2) + koff);
            }
            #pragma unroll
            for (int ni = 0; ni < 2; ni++) {
                mma_bf16(acc[ni], ah, bh[ni]);
                mma_bf16(acc[ni], ah, bl[ni]);
                mma_bf16(acc[ni], al, bh[ni]);
            }
        }
        __syncthreads();
        if (k + 2 < 8) issue(k + 2, stg);
    }

    #pragma unroll
    for (int ni = 0; ni < 2; ni++) {
        int col = wn*16 + ni*8 + (lane&3)*2;
        float* base = (col < 16) ? g_Bm : g_Cm;
        int cb = col & 15;
        size_t row = r0 + wm*16 + (lane>>2);
        *(float2*)&base[row*NS + cb]     = make_float2(acc[ni][0], acc[ni][1]);
        *(float2*)&base[(row+8)*NS + cb] = make_float2(acc[ni][2], acc[ni][3]);
    }
}

// ---------------- K3 (S1): per-chunk local scan -> P ------------------------
__global__ void k_scan1() {
    __shared__ float sB[CL*NS];
    int b = blockIdx.y, ch = blockIdx.x;
    int tid = threadIdx.x;
    int t0 = ch * CL;
    for (int i = tid; i < CL*NS; i += 256)
        sB[i] = g_Bm[((size_t)b*NPT + t0)*NS + i];
    __syncthreads();
    float A[NS], h[NS];
    #pragma unroll
    for (int s = 0; s < NS; s++) { A[s] = g_A[tid*NS + s]; h[s] = 0.f; }
    const float* dptr = g_deltaT + ((size_t)b*NPT + t0)*DI + tid;
    for (int k = 0; k < CL; k++) {
        float dl = dptr[(size_t)k*DI];
        const float* Bk = &sB[k*NS];
        #pragma unroll
        for (int s = 0; s < NS; s++)
            h[s] = fmaf(A[s], h[s], dl * Bk[s]);
    }
    float* P = g_P + ((size_t)b*NC + ch)*NS*DI + tid;
    #pragma unroll
    for (int s = 0; s < NS; s++) P[s*DI] = h[s];
}

// ---------------- K4 (S2): inter-chunk prefix --------------------------------
__global__ void k_scan2() {
    int g = blockIdx.x * 256 + threadIdx.x;
    int d = g & 255;
    int s = (g >> 8) & 15;
    int b = g >> 12;
    float aL = g_aL[d*NS + s];
    float h = 0.f;
    size_t base = ((size_t)b*NC*NS + s)*DI + d;
    for (int c = 0; c < NC; c++) {
        size_t idx = base + (size_t)c*NS*DI;
        g_H0[idx] = h;
        h = fmaf(aL, h, g_P[idx]);
    }
}

// ---------------- K5 (S3): final scan + y hi/lo bf16 -------------------------
__global__ void k_scan3(const float* __restrict__ Dskip) {
    __shared__ float sB[CL*NS], sC[CL*NS];
    int b = blockIdx.y, ch = blockIdx.x;
    int tid = threadIdx.x;
    int t0 = ch * CL;
    for (int i = tid; i < CL*NS; i += 256) {
        sB[i] = g_Bm[((size_t)b*NPT + t0)*NS + i];
        sC[i] = g_Cm[((size_t)b*NPT + t0)*NS + i];
    }
    __syncthreads();
    float A[NS], h[NS];
    size_t hbase = ((size_t)b*NC + ch)*NS*DI + tid;
    #pragma unroll
    for (int s = 0; s < NS; s++) { A[s] = g_A[tid*NS + s]; h[s] = g_H0[hbase + s*DI]; }
    float dsk = Dskip[tid];
    const float* dptr = g_deltaT + ((size_t)b*NPT + t0)*DI + tid;
    const __nv_bfloat16* xhp = g_xshi + ((size_t)b*NPT + t0)*DI + tid;
    const __nv_bfloat16* xlp = g_xslo + ((size_t)b*NPT + t0)*DI + tid;
    __nv_bfloat16* yh = g_yhi + ((size_t)b*NPT + t0)*DI + tid;
    __nv_bfloat16* yl = g_ylo + ((size_t)b*NPT + t0)*DI + tid;
    for (int k = 0; k < CL; k++) {
        float dl = dptr[(size_t)k*DI];
        float xv = __bfloat162float(xhp[(size_t)k*DI]) + __bfloat162float(xlp[(size_t)k*DI]);
        const float* Bk = &sB[k*NS];
        const float* Ck = &sC[k*NS];
        float y = dsk * xv;
        #pragma unroll
        for (int s = 0; s < NS; s++) {
            h[s] = fmaf(A[s], h[s], dl * Bk[s]);
            y = fmaf(h[s], Ck[s], y);
        }
        __nv_bfloat16 hi = __float2bfloat16(y);
        yh[(size_t)k*DI] = hi;
        yl[(size_t)k*DI] = __float2bfloat16(y - __bfloat162float(hi));
    }
}

// ---------------- K6: fused out_proj + bias + residual + LN + store ----------
// Block: 128 rows (one b, 128 n) x all 256 cols. 512 threads = 16 warps (4m x 4n).
#define OL_A_B (128*SAS*2)          // one A array (128 rows)
#define OL_B_B (256*SAS*2)          // one B array (256 rows)
#define OL_STG (2*OL_A_B + 2*OL_B_B)   // 61440
#define OL_DSM (2*OL_STG)              // 122880
__global__ void __launch_bounds__(512) k_mma_out_ln(
    const float* __restrict__ x, const float* __restrict__ bout,
    const float* __restrict__ gamma, const float* __restrict__ beta,
    float* __restrict__ out) {
    extern __shared__ char dsm[];
    uint32_t sb = smem_u32(dsm);
    int tid = threadIdx.x, lane = tid & 31, wid = tid >> 5;
    int wm = wid & 3, wn = wid >> 2;      // 4 m-groups (32 rows) x 4 n-groups (64 cols)
    size_t r0 = (size_t)blockIdx.x * 128; // rows over (b,n); one b per block
    int b = (int)(r0 >> 12);
    int n0 = (int)(r0 & 4095);

    float acc[2][8][4];
    #pragma unroll
    for (int i = 0; i < 2; i++)
        #pragma unroll
        for (int j = 0; j < 8; j++)
            #pragma unroll
            for (int q = 0; q < 4; q++) acc[i][j][q] = 0.f;

    auto issue = [&](int k, int stg) {
        uint32_t sbase = sb + (uint32_t)stg*OL_STG;
        int k0 = k*32;
        #pragma unroll
        for (int i = 0; i < 2; i++) {          // A: yhi/ylo, 1024 cp
            int idx = tid + i*512;
            int arr = idx >> 9, rem = idx & 511;
            int row = rem >> 2, seg = rem & 3;
            uint32_t so = (uint32_t)arr*OL_A_B + (uint32_t)((row*SAS + seg*8)*2);
            size_t g = (r0 + row)*DI + k0 + seg*8;
            cpa16(sbase + so, arr ? (const void*)&g_ylo[g] : (const void*)&g_yhi[g]);
        }
        #pragma unroll
        for (int i = 0; i < 4; i++) {          // B: wohi/wolo, 2048 cp
            int idx = tid + i*512;
            int arr = idx >> 10, rem = idx & 1023;
            int row = rem >> 2, seg = rem & 3;
            uint32_t so = 2*OL_A_B + (uint32_t)arr*OL_B_B + (uint32_t)((row*SAS + seg*8)*2);
            size_t g = (size_t)row*DI + k0 + seg*8;
            cpa16(sbase + so, arr ? (const void*)&g_wolo[g] : (const void*)&g_wohi[g]);
        }
        CPA_COMMIT();
    };

    uint32_t aoff = (uint32_t)(((wm*32 + (lane&15))*SAS + (lane>>4)*8) * 2);
    uint32_t boff = 2*OL_A_B + (uint32_t)(((wn*64 + (lane&7))*SAS + ((lane>>3)&1)*8) * 2);

    issue(0, 0);
    issue(1, 1);

    #pragma unroll
    for (int k = 0; k < 8; k++) {
        if (k < 7) asm volatile("cp.async.wait_group 1;" ::: "memory");
        else       asm volatile("cp.async.wait_group 0;" ::: "memory");
        __syncthreads();
        int stg = k & 1;
        uint32_t aBase = sb + (uint32_t)stg*OL_STG + aoff;
        uint32_t bBase = sb + (uint32_t)stg*OL_STG + boff;
        #pragma unroll
        for (int ks = 0; ks < 2; ks++) {
            uint32_t koff = ks*32;
            uint32_t ah[2][4], al[2][4], bh[8][2], bl[8][2];
            #pragma unroll
            for (int mi = 0; mi < 2; mi++) {
                ldsm4(ah[mi], aBase + mi*(16*SAS*2) + koff);
                ldsm4(al[mi], aBase + OL_A_B + mi*(16*SAS*2) + koff);
            }
            #pragma unroll
            for (int ni = 0; ni < 8; ni++) {
                ldsm2(bh[ni], bBase + ni*(8*SAS*2) + koff);
                ldsm2(bl[ni], bBase + OL_B_B + ni*(8*SAS*2) + koff);
            }
            #pragma unroll
            for (int mi = 0; mi < 2; mi++)
                #pragma unroll
                for (int ni = 0; ni < 8; ni++) {
                    mma_bf16(acc[mi][ni], ah[mi], bh[ni]);
                    mma_bf16(acc[mi][ni], ah[mi], bl[ni]);
                    mma_bf16(acc[mi][ni], al[mi], bh[ni]);
                }
        }
        __syncthreads();
        if (k + 2 < 8) issue(k + 2, stg);
    }
    __syncthreads();

    // ---- epilogue: 4 chunks of 32 rows; stage[c][nn] fp32, stride 36 ----
    float* stage = (float*)dsm;          // 256*36 floats = 36864 B
    float* mu = (float*)(dsm + 256*36*4);
    float* rs = mu + 32;
    for (int p = 0; p < 4; p++) {
        // 1. warps with wm==p stage acc+bias
        if (wm == p) {
            #pragma unroll
            for (int mi = 0; mi < 2; mi++) {
                int rl = mi*16 + (lane>>2);
                #pragma unroll
                for (int ni = 0; ni < 8; ni++) {
                    int c = wn*64 + ni*8 + (lane&3)*2;
                    float b0 = bout[c], b1 = bout[c+1];
                    stage[(size_t)c*36 + rl]         = acc[mi][ni][0] + b0;
                    stage[(size_t)(c+1)*36 + rl]     = acc[mi][ni][1] + b1;
                    stage[(size_t)c*36 + rl + 8]     = acc[mi][ni][2] + b0;
                    stage[(size_t)(c+1)*36 + rl + 8] = acc[mi][ni][3] + b1;
                }
            }
        }
        __syncthreads();
        // 2. residual from x, coalesced over n
        int nb = n0 + p*32;
        for (int idx = tid; idx < 8192; idx += 512) {
            int c = idx >> 5, nn = idx & 31;
            stage[(size_t)c*36 + nn] += x[((size_t)b*DIMC + c)*NPT + nb + nn];
        }
        __syncthreads();
        // 3. per-row stats: 16 warps x 2 half-warps -> 32 rows
        {
            int nn = wid*2 + (lane>>4);
            int h = lane & 15;
            float sum = 0.f, sq = 0.f;
            #pragma unroll
            for (int c = h; c < 256; c += 16) {
                float v = stage[(size_t)c*36 + nn];
                sum += v; sq += v*v;
            }
            #pragma unroll
            for (int o = 1; o < 16; o <<= 1) {
                sum += __shfl_xor_sync(0xFFFFFFFFu, sum, o);
                sq  += __shfl_xor_sync(0xFFFFFFFFu, sq,  o);
            }
            if (h == 0) {
                float m = sum * (1.f/256.f);
                mu[nn] = m;
                rs[nn] = rsqrtf(sq * (1.f/256.f) - m*m + 1e-5f);
            }
        }
        __syncthreads();
        // 4. normalize + write out[b][c][n], coalesced over n
        for (int idx = tid; idx < 8192; idx += 512) {
            int c = idx >> 5, nn = idx & 31;
            float v = (stage[(size_t)c*36 + nn] - mu[nn]) * rs[nn] * gamma[c] + beta[c];
            out[((size_t)b*DIMC + c)*NPT + nb + nn] = v;
        }
        __syncthreads();
    }
}

// ---------------- launch ------------------------------------------------------
extern "C" void kernel_launch(void* const* d_in, const int* in_sizes, int n_in,
                              void* d_out, int out_size) {
    const float* x      = (const float*)d_in[0];
    const float* w_in   = (const float*)d_in[1];
    const float* b_in   = (const float*)d_in[2];
    const float* w_conv = (const float*)d_in[3];
    const float* b_conv = (const float*)d_in[4];
    const float* A_log  = (const float*)d_in[5];
    const float* D_skip = (const float*)d_in[6];
    const float* Bw     = (const float*)d_in[7];
    const float* Cw     = (const float*)d_in[8];
    const float* w_out  = (const float*)d_in[9];
    const float* b_out  = (const float*)d_in[10];
    const float* gamma  = (const float*)d_in[11];
    const float* beta   = (const float*)d_in[12];
    float* out = (float*)d_out;

    cudaFuncSetAttribute(k_mma_in,     cudaFuncAttributeMaxDynamicSharedMemorySize, MMA_DSM);
    cudaFuncSetAttribute(k_mma_out_ln, cudaFuncAttributeMaxDynamicSharedMemorySize, OL_DSM);

    k_prep<<<816 + 4096, 256>>>(A_log, w_in, w_out, Bw, Cw, x);
    k_mma_in<<<dim3(32, 4, BATCH), 256, MMA_DSM>>>(b_in);
    k_convz<<<dim3(32, 8, BATCH), 256>>>(w_conv, b_conv);
    k_mma_bc<<<256, 256>>>();
    k_scan1<<<dim3(NC, BATCH), 256>>>();
    k_scan2<<<64, 256>>>();
    k_scan3<<<dim3(NC, BATCH), 256>>>(D_skip);
    k_mma_out_ln<<<128, 512, OL_DSM>>>(x, b_out, gamma, beta, out);
}